// round 3
// baseline (speedup 1.0000x reference)
#include <cuda_runtime.h>
#include <math.h>

// Problem constants
#define Cc 256
#define Vv 17
#define Bb 4
#define Tt 256
#define Nr 1024            // B*T
#define Pp 17408           // Nr*Vv
#define DIN 1024
#define NY 18432           // Nr*18
#define TOTAL 4456448      // B*C*V*T
#define INV_SQRT_DK 0.17677669529663687f

// 0-indexed adjacency (padded), degrees
__constant__ int c_nbr[17][5] = {
    {0,1,2,5,6},{0,1,3,0,0},{0,2,4,0,0},{1,3,0,0,0},{2,4,0,0,0},
    {0,5,7,11,0},{0,6,8,12,0},{5,7,9,0,0},{6,8,12,0,0},{7,9,0,0,0},
    {8,10,0,0,0},{8,11,13,0,0},{10,12,14,0,0},{11,13,15,0,0},{12,14,16,0,0},
    {13,15,0,0,0},{14,16,0,0,0}
};
__constant__ int c_deg[17] = {5,3,3,2,2,4,4,3,3,2,2,3,3,3,3,2,2};

// Scratch (device globals; allocation-free)
__device__ float g_X[Pp*Cc];
__device__ float g_embs[Pp*Cc];
__device__ float g_xn[Pp*Cc];
__device__ float g_Q[Pp*Cc];
__device__ float g_Kx[Pp*Cc];
__device__ float g_Vx[Pp*Cc];
__device__ float g_AKe[Pp*Cc];
__device__ float g_AVe[Pp*Cc];
__device__ float g_AKr[Nr*Cc];
__device__ float g_AVr[Nr*Cc];
__device__ float g_relay0[Nr*Cc];
__device__ float g_relay[Nr*Cc];
__device__ float g_y1[Pp*Cc];
__device__ float g_ret[Pp*Cc];
__device__ float g_H[Pp*DIN];
__device__ float g_F[Pp*Cc];
__device__ float g_Ybuf[NY*Cc];
__device__ float g_QR[Nr*Cc];
__device__ float g_KY[NY*Cc];
__device__ float g_VY[NY*Cc];
__device__ float g_yr[Nr*Cc];
__device__ float g_retr[Nr*Cc];
__device__ float g_Hr[Nr*DIN];
__device__ float g_Fr[Nr*Cc];
__device__ float g_stats[2*Cc];

// ---------------- layout / prep ----------------
__global__ void prep_kernel(const float* __restrict__ data,
                            float* __restrict__ X, float* __restrict__ E)
{
    int idx = blockIdx.x * blockDim.x + threadIdx.x;
    if (idx >= TOTAL) return;
    int t = idx % Tt;
    int v = (idx / Tt) % Vv;
    int c = (idx / (Tt * Vv)) % Cc;
    int b = idx / (Tt * Vv * Cc);
    float val = data[idx];
    size_t p = (size_t)((b * Tt + t) * Vv + v);
    X[p * Cc + c] = val;
    E[p * Cc + c] = val;
}

__global__ void relay_init_kernel(const float* __restrict__ X,
                                  float* __restrict__ r0, float* __restrict__ r)
{
    int idx = blockIdx.x * blockDim.x + threadIdx.x;
    if (idx >= Nr * Cc) return;
    int n = idx >> 8;
    int c = idx & 255;
    float s = 0.f;
    #pragma unroll
    for (int v = 0; v < Vv; v++) s += X[(size_t)(n * Vv + v) * Cc + c];
    s *= (1.0f / Vv);
    r0[idx] = s;
    r[idx] = s;
}

__global__ void final_kernel(const float* __restrict__ X, float* __restrict__ out)
{
    int idx = blockIdx.x * blockDim.x + threadIdx.x;
    if (idx >= TOTAL) return;
    int t = idx % Tt;
    int v = (idx / Tt) % Vv;
    int c = (idx / (Tt * Vv)) % Cc;
    int b = idx / (Tt * Vv * Cc);
    out[idx] = X[(size_t)((b * Tt + t) * Vv + v) * Cc + c];
}

// ---------------- LayerNorm over channels (per row) ----------------
__global__ void __launch_bounds__(256) ln_kernel(const float* __restrict__ x,
                                                 const float* __restrict__ g,
                                                 const float* __restrict__ b,
                                                 float* __restrict__ y, int rows)
{
    int row = blockIdx.x * 8 + (threadIdx.x >> 5);
    int lane = threadIdx.x & 31;
    if (row >= rows) return;
    const float* xr = x + (size_t)row * Cc;
    float v[8];
    float s = 0.f;
    #pragma unroll
    for (int i = 0; i < 8; i++) { v[i] = xr[lane + 32 * i]; s += v[i]; }
    #pragma unroll
    for (int o = 16; o; o >>= 1) s += __shfl_xor_sync(~0u, s, o);
    float mean = s * (1.0f / Cc);
    float s2 = 0.f;
    #pragma unroll
    for (int i = 0; i < 8; i++) { float d = v[i] - mean; s2 += d * d; }
    #pragma unroll
    for (int o = 16; o; o >>= 1) s2 += __shfl_xor_sync(~0u, s2, o);
    float rs = rsqrtf(s2 * (1.0f / Cc) + 1e-6f);
    float* yr = y + (size_t)row * Cc;
    #pragma unroll
    for (int i = 0; i < 8; i++) {
        int c = lane + 32 * i;
        yr[c] = (v[i] - mean) * rs * g[c] + b[c];
    }
}

// ---------------- SGEMM: out[M,N] = A[M,K] @ W[N,K]^T (+bias)(+res)(relu) ----------------
// Requires M%64==0, N%64==0, K%16==0.
__global__ void __launch_bounds__(256) sgemm(const float* __restrict__ A,
                                             const float* __restrict__ W,
                                             const float* __restrict__ bias,
                                             const float* __restrict__ res,
                                             float* __restrict__ out,
                                             int M, int N, int K, int relu)
{
    __shared__ float As[16][64];
    __shared__ float Ws[16][64];
    const int bm = blockIdx.y * 64;
    const int bn = blockIdx.x * 64;
    const int tid = threadIdx.x;
    const int tr = tid >> 4;
    const int tc = tid & 15;
    const int lrow = tid >> 2;
    const int lk = (tid & 3) << 2;
    float acc[4][4] = {};
    const float* Aptr = A + (size_t)(bm + lrow) * K + lk;
    const float* Wptr = W + (size_t)(bn + lrow) * K + lk;
    for (int k0 = 0; k0 < K; k0 += 16) {
        float4 a4 = *(const float4*)(Aptr + k0);
        float4 w4 = *(const float4*)(Wptr + k0);
        As[lk + 0][lrow] = a4.x; As[lk + 1][lrow] = a4.y;
        As[lk + 2][lrow] = a4.z; As[lk + 3][lrow] = a4.w;
        Ws[lk + 0][lrow] = w4.x; Ws[lk + 1][lrow] = w4.y;
        Ws[lk + 2][lrow] = w4.z; Ws[lk + 3][lrow] = w4.w;
        __syncthreads();
        #pragma unroll
        for (int kk = 0; kk < 16; kk++) {
            float4 af = *(const float4*)&As[kk][tr << 2];
            float4 wf = *(const float4*)&Ws[kk][tc << 2];
            float a[4] = {af.x, af.y, af.z, af.w};
            float w[4] = {wf.x, wf.y, wf.z, wf.w};
            #pragma unroll
            for (int i = 0; i < 4; i++)
                #pragma unroll
                for (int j = 0; j < 4; j++)
                    acc[i][j] = fmaf(a[i], w[j], acc[i][j]);
        }
        __syncthreads();
    }
    #pragma unroll
    for (int i = 0; i < 4; i++) {
        int r = bm + (tr << 2) + i;
        #pragma unroll
        for (int j = 0; j < 4; j++) {
            int c = bn + (tc << 2) + j;
            float v = acc[i][j];
            if (bias) v += bias[c];
            if (res)  v += res[(size_t)r * N + c];
            if (relu) v = fmaxf(v, 0.0f);
            out[(size_t)r * N + c] = v;
        }
    }
}

// ---------------- graph attention (7 slots) ----------------
__global__ void __launch_bounds__(256) attn_j(const float* __restrict__ Q,
                                              const float* __restrict__ Kx,
                                              const float* __restrict__ Vx,
                                              const float* __restrict__ AKe,
                                              const float* __restrict__ AVe,
                                              const float* __restrict__ AKr,
                                              const float* __restrict__ AVr,
                                              const float* __restrict__ xn,
                                              float* __restrict__ y1)
{
    int p = blockIdx.x;
    int h = threadIdx.x >> 5;
    int lane = threadIdx.x & 31;
    int n = p / Vv, l = p - n * Vv;
    int co = (h << 5) + lane;
    size_t base = (size_t)p * Cc + co;
    size_t nbase = (size_t)n * Cc + co;
    float q = Q[base];
    int deg = c_deg[l];
    float sc[7];
    #pragma unroll
    for (int w = 0; w < 5; w++) {
        float d = -1e30f;
        if (w < deg) {
            int j = c_nbr[l][w];
            float dd = q * Kx[(size_t)(n * Vv + j) * Cc + co];
            #pragma unroll
            for (int o = 16; o; o >>= 1) dd += __shfl_xor_sync(~0u, dd, o);
            d = dd * INV_SQRT_DK;
        }
        sc[w] = d;
    }
    {
        float dd = q * AKe[base];
        #pragma unroll
        for (int o = 16; o; o >>= 1) dd += __shfl_xor_sync(~0u, dd, o);
        sc[5] = dd * INV_SQRT_DK;
        dd = q * AKr[nbase];
        #pragma unroll
        for (int o = 16; o; o >>= 1) dd += __shfl_xor_sync(~0u, dd, o);
        sc[6] = dd * INV_SQRT_DK;
    }
    float mx = sc[0];
    #pragma unroll
    for (int w = 1; w < 7; w++) mx = fmaxf(mx, sc[w]);
    float wg[7];
    float sum = 0.f;
    #pragma unroll
    for (int w = 0; w < 7; w++) { wg[w] = expf(sc[w] - mx); sum += wg[w]; }
    float att = 0.f;
    #pragma unroll
    for (int w = 0; w < 5; w++)
        if (w < deg) att += wg[w] * Vx[(size_t)(n * Vv + c_nbr[l][w]) * Cc + co];
    att += wg[5] * AVe[base] + wg[6] * AVr[nbase];
    y1[base] = xn[base] + att / sum;
}

// ---------------- relay attention (18 slots) ----------------
__global__ void __launch_bounds__(256) attn_r(const float* __restrict__ QR,
                                              const float* __restrict__ KY,
                                              const float* __restrict__ VY,
                                              const float* __restrict__ relay,
                                              float* __restrict__ yr)
{
    int n = blockIdx.x;
    int h = threadIdx.x >> 5;
    int lane = threadIdx.x & 31;
    int co = (h << 5) + lane;
    size_t nbase = (size_t)n * Cc + co;
    float q = QR[nbase];
    float sc[18];
    float mx = -1e30f;
    #pragma unroll
    for (int m = 0; m < 18; m++) {
        float dd = q * KY[(size_t)(n * 18 + m) * Cc + co];
        #pragma unroll
        for (int o = 16; o; o >>= 1) dd += __shfl_xor_sync(~0u, dd, o);
        dd *= INV_SQRT_DK;
        sc[m] = dd;
        mx = fmaxf(mx, dd);
    }
    float sum = 0.f;
    #pragma unroll
    for (int m = 0; m < 18; m++) { sc[m] = expf(sc[m] - mx); sum += sc[m]; }
    float att = 0.f;
    #pragma unroll
    for (int m = 0; m < 18; m++) att += sc[m] * VY[(size_t)(n * 18 + m) * Cc + co];
    yr[nbase] = relay[nbase] + att / sum;
}

// ---------------- BatchNorm (axes 0,2) ----------------
__global__ void bn_zero(float* __restrict__ stats)
{
    int i = blockIdx.x * blockDim.x + threadIdx.x;
    if (i < 2 * Cc) stats[i] = 0.f;
}

__global__ void __launch_bounds__(256) bn_stats(const float* __restrict__ x,
                                                float* __restrict__ stats, int rows)
{
    int c = threadIdx.x;
    int r0 = blockIdx.x * 64;
    float s = 0.f, s2 = 0.f;
    for (int r = r0; r < r0 + 64; r++) {
        float v = x[(size_t)r * Cc + c];
        s += v; s2 += v * v;
    }
    atomicAdd(&stats[c], s);
    atomicAdd(&stats[Cc + c], s2);
}

__global__ void __launch_bounds__(256) bn_apply(const float* __restrict__ x,
                                                const float* __restrict__ stats,
                                                const float* __restrict__ g,
                                                const float* __restrict__ b,
                                                float* __restrict__ y, int rows, int leaky)
{
    int idx = blockIdx.x * blockDim.x + threadIdx.x;
    if (idx >= rows * Cc) return;
    int c = idx & 255;
    float inv = 1.0f / rows;
    float mean = stats[c] * inv;
    float var = stats[Cc + c] * inv - mean * mean;
    float v = (x[idx] - mean) * rsqrtf(var + 1e-5f) * g[c] + b[c];
    if (leaky) v = v > 0.f ? v : 0.01f * v;
    y[idx] = v;
}

// ---------------- relay Y buffer: [relay | 17 nodes] ----------------
__global__ void ybuild(const float* __restrict__ relay,
                       const float* __restrict__ nodes, float* __restrict__ Y)
{
    int idx = blockIdx.x * blockDim.x + threadIdx.x;
    if (idx >= NY * Cc) return;
    int c = idx & 255;
    int row = idx >> 8;
    int n = row / 18;
    int m = row - n * 18;
    Y[idx] = (m == 0) ? relay[(size_t)n * Cc + c]
                      : nodes[(size_t)(n * Vv + m - 1) * Cc + c];
}

// ---------------- host ----------------
template <typename Sym>
static float* sym_addr(const Sym& s)
{
    void* p = nullptr;
    cudaGetSymbolAddress(&p, s);
    return (float*)p;
}

extern "C" void kernel_launch(void* const* d_in, const int* in_sizes, int n_in,
                              void* d_out, int out_size)
{
    const float* data  = (const float*)d_in[0];
    const float* ln_g  = (const float*)d_in[1];
    const float* ln_b  = (const float*)d_in[2];
    const float* jq_w  = (const float*)d_in[3];
    const float* jq_b  = (const float*)d_in[4];
    const float* jk_w  = (const float*)d_in[5];
    const float* jk_b  = (const float*)d_in[6];
    const float* jv_w  = (const float*)d_in[7];
    const float* jv_b  = (const float*)d_in[8];
    const float* jbn_g = (const float*)d_in[9];
    const float* jbn_b = (const float*)d_in[10];
    const float* jf1_w = (const float*)d_in[11];
    const float* jf1_b = (const float*)d_in[12];
    const float* jf2_w = (const float*)d_in[13];
    const float* jf2_b = (const float*)d_in[14];
    const float* jfbn_g = (const float*)d_in[15];
    const float* jfbn_b = (const float*)d_in[16];
    const float* rq_w  = (const float*)d_in[17];
    const float* rq_b  = (const float*)d_in[18];
    const float* rk_w  = (const float*)d_in[19];
    const float* rk_b  = (const float*)d_in[20];
    const float* rv_w  = (const float*)d_in[21];
    const float* rv_b  = (const float*)d_in[22];
    const float* rbn_g = (const float*)d_in[23];
    const float* rbn_b = (const float*)d_in[24];
    const float* rf1_w = (const float*)d_in[25];
    const float* rf1_b = (const float*)d_in[26];
    const float* rf2_w = (const float*)d_in[27];
    const float* rf2_b = (const float*)d_in[28];
    const float* rfbn_g = (const float*)d_in[29];
    const float* rfbn_b = (const float*)d_in[30];

    float* X     = sym_addr(g_X);
    float* embs  = sym_addr(g_embs);
    float* xn    = sym_addr(g_xn);
    float* Q     = sym_addr(g_Q);
    float* Kx    = sym_addr(g_Kx);
    float* Vx    = sym_addr(g_Vx);
    float* AKe   = sym_addr(g_AKe);
    float* AVe   = sym_addr(g_AVe);
    float* AKr   = sym_addr(g_AKr);
    float* AVr   = sym_addr(g_AVr);
    float* relay0 = sym_addr(g_relay0);
    float* relay = sym_addr(g_relay);
    float* y1    = sym_addr(g_y1);
    float* ret   = sym_addr(g_ret);
    float* H     = sym_addr(g_H);
    float* F     = sym_addr(g_F);
    float* Ybuf  = sym_addr(g_Ybuf);
    float* QR    = sym_addr(g_QR);
    float* KY    = sym_addr(g_KY);
    float* VY    = sym_addr(g_VY);
    float* yr    = sym_addr(g_yr);
    float* retr  = sym_addr(g_retr);
    float* Hr    = sym_addr(g_Hr);
    float* Fr    = sym_addr(g_Fr);
    float* stats = sym_addr(g_stats);

    prep_kernel<<<(TOTAL + 255) / 256, 256>>>(data, X, embs);
    relay_init_kernel<<<(Nr * Cc + 255) / 256, 256>>>(X, relay0, relay);

    for (int ly = 0; ly < 2; ly++) {
        const float* lg  = ln_g + ly * Cc;
        const float* lb  = ln_b + ly * Cc;
        const float* qw  = jq_w + (size_t)ly * Cc * Cc;
        const float* qb  = jq_b + ly * Cc;
        const float* kw  = jk_w + (size_t)ly * Cc * Cc;
        const float* kb  = jk_b + ly * Cc;
        const float* vw  = jv_w + (size_t)ly * Cc * Cc;
        const float* vb  = jv_b + ly * Cc;
        const float* bng = jbn_g + ly * Cc;
        const float* bnb = jbn_b + ly * Cc;
        const float* f1w = jf1_w + (size_t)ly * DIN * Cc;
        const float* f1b = jf1_b + ly * DIN;
        const float* f2w = jf2_w + (size_t)ly * Cc * DIN;
        const float* f2b = jf2_b + ly * Cc;
        const float* fbg = jfbn_g + ly * Cc;
        const float* fbb = jfbn_b + ly * Cc;

        // ---- node (sju) path ----
        ln_kernel<<<Pp / 8, 256>>>(X, lg, lb, xn, Pp);

        dim3 gP(Cc / 64, Pp / 64);
        sgemm<<<gP, 256>>>(xn,   qw, qb, nullptr, Q,   Pp, Cc, Cc, 0);
        sgemm<<<gP, 256>>>(xn,   kw, kb, nullptr, Kx,  Pp, Cc, Cc, 0);
        sgemm<<<gP, 256>>>(xn,   vw, vb, nullptr, Vx,  Pp, Cc, Cc, 0);
        sgemm<<<gP, 256>>>(embs, kw, kb, nullptr, AKe, Pp, Cc, Cc, 0);
        sgemm<<<gP, 256>>>(embs, vw, vb, nullptr, AVe, Pp, Cc, Cc, 0);
        dim3 gN(Cc / 64, Nr / 64);
        sgemm<<<gN, 256>>>(relay0, kw, kb, nullptr, AKr, Nr, Cc, Cc, 0);
        sgemm<<<gN, 256>>>(relay0, vw, vb, nullptr, AVr, Nr, Cc, Cc, 0);

        attn_j<<<Pp, 256>>>(Q, Kx, Vx, AKe, AVe, AKr, AVr, xn, y1);

        bn_zero<<<2, 256>>>(stats);
        bn_stats<<<Pp / 64, 256>>>(y1, stats, Pp);
        bn_apply<<<(Pp * Cc + 255) / 256, 256>>>(y1, stats, bng, bnb, ret, Pp, 0);

        dim3 gF1(DIN / 64, Pp / 64);
        sgemm<<<gF1, 256>>>(ret, f1w, f1b, nullptr, H, Pp, DIN, Cc, 1);
        dim3 gF2(Cc / 64, Pp / 64);
        sgemm<<<gF2, 256>>>(H, f2w, f2b, ret, F, Pp, Cc, DIN, 0);

        bn_zero<<<2, 256>>>(stats);
        bn_stats<<<Pp / 64, 256>>>(F, stats, Pp);
        bn_apply<<<(Pp * Cc + 255) / 256, 256>>>(F, stats, fbg, fbb, X, Pp, 1);

        // ---- relay (sru) path ----
        const float* rqw = rq_w + (size_t)ly * Cc * Cc;
        const float* rqb = rq_b + ly * Cc;
        const float* rkw = rk_w + (size_t)ly * Cc * Cc;
        const float* rkb = rk_b + ly * Cc;
        const float* rvw = rv_w + (size_t)ly * Cc * Cc;
        const float* rvb = rv_b + ly * Cc;
        const float* rbg = rbn_g + ly * Cc;
        const float* rbb = rbn_b + ly * Cc;
        const float* rf1w2 = rf1_w + (size_t)ly * DIN * Cc;
        const float* rf1b2 = rf1_b + ly * DIN;
        const float* rf2w2 = rf2_w + (size_t)ly * Cc * DIN;
        const float* rf2b2 = rf2_b + ly * Cc;
        const float* rfg = rfbn_g + ly * Cc;
        const float* rfb = rfbn_b + ly * Cc;

        ybuild<<<(NY * Cc + 255) / 256, 256>>>(relay, X, Ybuf);
        sgemm<<<gN, 256>>>(relay, rqw, rqb, nullptr, QR, Nr, Cc, Cc, 0);
        dim3 gY(Cc / 64, NY / 64);
        sgemm<<<gY, 256>>>(Ybuf, rkw, rkb, nullptr, KY, NY, Cc, Cc, 0);
        sgemm<<<gY, 256>>>(Ybuf, rvw, rvb, nullptr, VY, NY, Cc, Cc, 0);

        attn_r<<<Nr, 256>>>(QR, KY, VY, relay, yr);

        bn_zero<<<2, 256>>>(stats);
        bn_stats<<<Nr / 64, 256>>>(yr, stats, Nr);
        bn_apply<<<(Nr * Cc + 255) / 256, 256>>>(yr, stats, rbg, rbb, retr, Nr, 0);

        dim3 gR1(DIN / 64, Nr / 64);
        sgemm<<<gR1, 256>>>(retr, rf1w2, rf1b2, nullptr, Hr, Nr, DIN, Cc, 1);
        dim3 gR2(Cc / 64, Nr / 64);
        sgemm<<<gR2, 256>>>(Hr, rf2w2, rf2b2, retr, Fr, Nr, Cc, DIN, 0);

        bn_zero<<<2, 256>>>(stats);
        bn_stats<<<Nr / 64, 256>>>(Fr, stats, Nr);
        bn_apply<<<(Nr * Cc + 255) / 256, 256>>>(Fr, stats, rfg, rfb, relay, Nr, 1);
    }

    final_kernel<<<(TOTAL + 255) / 256, 256>>>(X, (float*)d_out);
}

// round 4
// speedup vs baseline: 1.6125x; 1.6125x over previous
#include <cuda_runtime.h>
#include <math.h>

// Problem constants
#define Cc 256
#define Vv 17
#define Tt 256
#define Nr 1024            // B*T
#define Pp 17408           // Nr*Vv
#define DIN 1024
#define TOTAL 4456448      // B*C*V*T
#define INV_SQRT_DK 0.17677669529663687f

// 0-indexed adjacency (padded), degrees
__constant__ int c_nbr[17][5] = {
    {0,1,2,5,6},{0,1,3,0,0},{0,2,4,0,0},{1,3,0,0,0},{2,4,0,0,0},
    {0,5,7,11,0},{0,6,8,12,0},{5,7,9,0,0},{6,8,12,0,0},{7,9,0,0,0},
    {8,10,0,0,0},{8,11,13,0,0},{10,12,14,0,0},{11,13,15,0,0},{12,14,16,0,0},
    {13,15,0,0,0},{14,16,0,0,0}
};
__constant__ int c_deg[17] = {5,3,3,2,2,4,4,3,3,2,2,3,3,3,3,2,2};

// Scratch (device globals; allocation-free)
__device__ float g_X[Pp*Cc];
__device__ float g_embs[Pp*Cc];
__device__ float g_xn[Pp*Cc];
__device__ float g_QKV[Pp*3*Cc];     // [Pp, 768]  (Q | K | V)
__device__ float g_AKV[Pp*2*Cc];     // [Pp, 512]  (AKe | AVe)
__device__ float g_AKVr[Nr*2*Cc];    // [Nr, 512]  (AKr | AVr)
__device__ float g_relay0[Nr*Cc];
__device__ float g_y1[Pp*Cc];
__device__ float g_ret[Pp*Cc];
__device__ float g_H[Pp*DIN];
__device__ float g_F[Pp*Cc];
__device__ float g_Wj[2*3*Cc*Cc];    // packed qkv weights per layer
__device__ float g_bj[2*3*Cc];       // packed qkv biases per layer
__device__ float g_stats[2*Cc];

// ---------------- layout / prep ----------------
__global__ void prep_kernel(const float* __restrict__ data,
                            float* __restrict__ X, float* __restrict__ E)
{
    int idx = blockIdx.x * blockDim.x + threadIdx.x;
    if (idx >= TOTAL) return;
    int t = idx % Tt;
    int v = (idx / Tt) % Vv;
    int c = (idx / (Tt * Vv)) % Cc;
    int b = idx / (Tt * Vv * Cc);
    float val = data[idx];
    size_t p = (size_t)((b * Tt + t) * Vv + v);
    X[p * Cc + c] = val;
    E[p * Cc + c] = val;
}

__global__ void relay_init_kernel(const float* __restrict__ X, float* __restrict__ r0)
{
    int idx = blockIdx.x * blockDim.x + threadIdx.x;
    if (idx >= Nr * Cc) return;
    int n = idx >> 8;
    int c = idx & 255;
    float s = 0.f;
    #pragma unroll
    for (int v = 0; v < Vv; v++) s += X[(size_t)(n * Vv + v) * Cc + c];
    r0[idx] = s * (1.0f / Vv);
}

__global__ void final_kernel(const float* __restrict__ X, float* __restrict__ out)
{
    int idx = blockIdx.x * blockDim.x + threadIdx.x;
    if (idx >= TOTAL) return;
    int t = idx % Tt;
    int v = (idx / Tt) % Vv;
    int c = (idx / (Tt * Vv)) % Cc;
    int b = idx / (Tt * Vv * Cc);
    out[idx] = X[(size_t)((b * Tt + t) * Vv + v) * Cc + c];
}

// ---------------- weight packing: [q;k;v] -> [3C, C] ----------------
__global__ void pack3(const float* __restrict__ q, const float* __restrict__ k,
                      const float* __restrict__ v,
                      const float* __restrict__ qb, const float* __restrict__ kb,
                      const float* __restrict__ vb,
                      float* __restrict__ W, float* __restrict__ b)
{
    int idx = blockIdx.x * blockDim.x + threadIdx.x;
    if (idx < 3 * Cc)
        b[idx] = (idx < Cc) ? qb[idx] : (idx < 2 * Cc) ? kb[idx - Cc] : vb[idx - 2 * Cc];
    if (idx >= 3 * Cc * Cc) return;
    int row = idx >> 8;
    int col = idx & 255;
    const float* src = (row < Cc) ? q + (size_t)row * Cc
                     : (row < 2 * Cc) ? k + (size_t)(row - Cc) * Cc
                     : v + (size_t)(row - 2 * Cc) * Cc;
    W[idx] = src[col];
}

// ---------------- LayerNorm over channels (per row) ----------------
__global__ void __launch_bounds__(256) ln_kernel(const float* __restrict__ x,
                                                 const float* __restrict__ g,
                                                 const float* __restrict__ b,
                                                 float* __restrict__ y, int rows)
{
    int row = blockIdx.x * 8 + (threadIdx.x >> 5);
    int lane = threadIdx.x & 31;
    if (row >= rows) return;
    const float* xr = x + (size_t)row * Cc;
    float v[8];
    float s = 0.f;
    #pragma unroll
    for (int i = 0; i < 8; i++) { v[i] = xr[lane + 32 * i]; s += v[i]; }
    #pragma unroll
    for (int o = 16; o; o >>= 1) s += __shfl_xor_sync(~0u, s, o);
    float mean = s * (1.0f / Cc);
    float s2 = 0.f;
    #pragma unroll
    for (int i = 0; i < 8; i++) { float d = v[i] - mean; s2 += d * d; }
    #pragma unroll
    for (int o = 16; o; o >>= 1) s2 += __shfl_xor_sync(~0u, s2, o);
    float rs = rsqrtf(s2 * (1.0f / Cc) + 1e-6f);
    float* yr = y + (size_t)row * Cc;
    #pragma unroll
    for (int i = 0; i < 8; i++) {
        int c = lane + 32 * i;
        yr[c] = (v[i] - mean) * rs * g[c] + b[c];
    }
}

// ---------------- SGEMM 128x128x8, 8x8 microtile, double-buffered ----------------
// out[M,N] = A[M,K] @ W[N,K]^T (+bias)(+res)(relu). M%128==0, N%128==0, K%8==0.
__global__ void __launch_bounds__(256, 2) sgemm128(const float* __restrict__ A,
                                                   const float* __restrict__ W,
                                                   const float* __restrict__ bias,
                                                   const float* __restrict__ res,
                                                   float* __restrict__ out,
                                                   int M, int N, int K, int relu)
{
    __shared__ float As[2][8][128];
    __shared__ float Ws[2][8][128];
    const int bm = blockIdx.y * 128;
    const int bn = blockIdx.x * 128;
    const int tid = threadIdx.x;
    const int lrow = tid >> 1;          // 0..127
    const int lcol = (tid & 1) << 2;    // 0 or 4
    const int tx = tid & 15;
    const int ty = tid >> 4;
    const float* Ag = A + (size_t)(bm + lrow) * K + lcol;
    const float* Wg = W + (size_t)(bn + lrow) * K + lcol;

    float acc[8][8] = {};

    // preload tile 0
    {
        float4 a = *(const float4*)Ag;
        float4 w = *(const float4*)Wg;
        As[0][lcol + 0][lrow] = a.x; As[0][lcol + 1][lrow] = a.y;
        As[0][lcol + 2][lrow] = a.z; As[0][lcol + 3][lrow] = a.w;
        Ws[0][lcol + 0][lrow] = w.x; Ws[0][lcol + 1][lrow] = w.y;
        Ws[0][lcol + 2][lrow] = w.z; Ws[0][lcol + 3][lrow] = w.w;
    }
    __syncthreads();

    const int KT = K >> 3;
    int buf = 0;
    for (int kt = 0; kt < KT; kt++) {
        float4 an, wn;
        const bool more = (kt + 1 < KT);
        if (more) {
            an = *(const float4*)(Ag + (kt + 1) * 8);
            wn = *(const float4*)(Wg + (kt + 1) * 8);
        }
        #pragma unroll
        for (int kk = 0; kk < 8; kk++) {
            float4 a0 = *(const float4*)&As[buf][kk][ty * 8];
            float4 a1 = *(const float4*)&As[buf][kk][ty * 8 + 4];
            float4 w0 = *(const float4*)&Ws[buf][kk][tx * 8];
            float4 w1 = *(const float4*)&Ws[buf][kk][tx * 8 + 4];
            float av[8] = {a0.x, a0.y, a0.z, a0.w, a1.x, a1.y, a1.z, a1.w};
            float wv[8] = {w0.x, w0.y, w0.z, w0.w, w1.x, w1.y, w1.z, w1.w};
            #pragma unroll
            for (int i = 0; i < 8; i++)
                #pragma unroll
                for (int j = 0; j < 8; j++)
                    acc[i][j] = fmaf(av[i], wv[j], acc[i][j]);
        }
        if (more) {
            buf ^= 1;
            As[buf][lcol + 0][lrow] = an.x; As[buf][lcol + 1][lrow] = an.y;
            As[buf][lcol + 2][lrow] = an.z; As[buf][lcol + 3][lrow] = an.w;
            Ws[buf][lcol + 0][lrow] = wn.x; Ws[buf][lcol + 1][lrow] = wn.y;
            Ws[buf][lcol + 2][lrow] = wn.z; Ws[buf][lcol + 3][lrow] = wn.w;
            __syncthreads();
        }
    }

    // epilogue
    float bv[8];
    if (bias) {
        float4 b0 = *(const float4*)(bias + bn + tx * 8);
        float4 b1 = *(const float4*)(bias + bn + tx * 8 + 4);
        bv[0]=b0.x; bv[1]=b0.y; bv[2]=b0.z; bv[3]=b0.w;
        bv[4]=b1.x; bv[5]=b1.y; bv[6]=b1.z; bv[7]=b1.w;
    } else {
        #pragma unroll
        for (int j = 0; j < 8; j++) bv[j] = 0.f;
    }
    #pragma unroll
    for (int i = 0; i < 8; i++) {
        size_t r = (size_t)(bm + ty * 8 + i);
        float* orow = out + r * N + bn + tx * 8;
        #pragma unroll
        for (int jj = 0; jj < 8; jj += 4) {
            float4 v = make_float4(acc[i][jj] + bv[jj], acc[i][jj + 1] + bv[jj + 1],
                                   acc[i][jj + 2] + bv[jj + 2], acc[i][jj + 3] + bv[jj + 3]);
            if (res) {
                float4 rr = *(const float4*)(res + r * N + bn + tx * 8 + jj);
                v.x += rr.x; v.y += rr.y; v.z += rr.z; v.w += rr.w;
            }
            if (relu) {
                v.x = fmaxf(v.x, 0.f); v.y = fmaxf(v.y, 0.f);
                v.z = fmaxf(v.z, 0.f); v.w = fmaxf(v.w, 0.f);
            }
            *(float4*)(orow + jj) = v;
        }
    }
}

// ---------------- graph attention (7 slots), packed inputs ----------------
// QKV: [Pp,768] (Q|K|V), AKV: [Pp,512] (AKe|AVe), AKVr: [Nr,512] (AKr|AVr)
__global__ void __launch_bounds__(256) attn_j(const float* __restrict__ QKV,
                                              const float* __restrict__ AKV,
                                              const float* __restrict__ AKVr,
                                              const float* __restrict__ xn,
                                              float* __restrict__ y1)
{
    int p = blockIdx.x;
    int lane = threadIdx.x & 31;
    int co = threadIdx.x;                 // 0..255
    int n = p / Vv, l = p - n * Vv;
    size_t qbase = (size_t)p * 768 + co;
    size_t abase = (size_t)p * 512 + co;
    size_t rbase = (size_t)n * 512 + co;
    float q = QKV[qbase];
    int deg = c_deg[l];
    float sc[7];
    #pragma unroll
    for (int w = 0; w < 5; w++) {
        float d = -1e30f;
        if (w < deg) {
            int j = c_nbr[l][w];
            float dd = q * QKV[(size_t)(n * Vv + j) * 768 + 256 + co];
            #pragma unroll
            for (int o = 16; o; o >>= 1) dd += __shfl_xor_sync(~0u, dd, o);
            d = dd * INV_SQRT_DK;
        }
        sc[w] = d;
    }
    {
        float dd = q * AKV[abase];
        #pragma unroll
        for (int o = 16; o; o >>= 1) dd += __shfl_xor_sync(~0u, dd, o);
        sc[5] = dd * INV_SQRT_DK;
        dd = q * AKVr[rbase];
        #pragma unroll
        for (int o = 16; o; o >>= 1) dd += __shfl_xor_sync(~0u, dd, o);
        sc[6] = dd * INV_SQRT_DK;
    }
    float mx = sc[0];
    #pragma unroll
    for (int w = 1; w < 7; w++) mx = fmaxf(mx, sc[w]);
    float wg[7];
    float sum = 0.f;
    #pragma unroll
    for (int w = 0; w < 7; w++) { wg[w] = expf(sc[w] - mx); sum += wg[w]; }
    float att = 0.f;
    #pragma unroll
    for (int w = 0; w < 5; w++)
        if (w < deg) att += wg[w] * QKV[(size_t)(n * Vv + c_nbr[l][w]) * 768 + 512 + co];
    att += wg[5] * AKV[abase + 256] + wg[6] * AKVr[rbase + 256];
    y1[(size_t)p * Cc + co] = xn[(size_t)p * Cc + co] + att / sum;
}

// ---------------- BatchNorm (axes 0,2) ----------------
__global__ void bn_zero(float* __restrict__ stats)
{
    int i = blockIdx.x * blockDim.x + threadIdx.x;
    if (i < 2 * Cc) stats[i] = 0.f;
}

__global__ void __launch_bounds__(256) bn_stats(const float* __restrict__ x,
                                                float* __restrict__ stats, int rows)
{
    int c = threadIdx.x;
    int r0 = blockIdx.x * 64;
    float s = 0.f, s2 = 0.f;
    for (int r = r0; r < r0 + 64; r++) {
        float v = x[(size_t)r * Cc + c];
        s += v; s2 += v * v;
    }
    atomicAdd(&stats[c], s);
    atomicAdd(&stats[Cc + c], s2);
}

__global__ void __launch_bounds__(256) bn_apply(const float* __restrict__ x,
                                                const float* __restrict__ stats,
                                                const float* __restrict__ g,
                                                const float* __restrict__ b,
                                                float* __restrict__ y, int rows, int leaky)
{
    int idx = blockIdx.x * blockDim.x + threadIdx.x;
    if (idx >= rows * Cc) return;
    int c = idx & 255;
    float inv = 1.0f / rows;
    float mean = stats[c] * inv;
    float var = stats[Cc + c] * inv - mean * mean;
    float v = (x[idx] - mean) * rsqrtf(var + 1e-5f) * g[c] + b[c];
    if (leaky) v = v > 0.f ? v : 0.01f * v;
    y[idx] = v;
}

// ---------------- host ----------------
template <typename Sym>
static float* sym_addr(const Sym& s)
{
    void* p = nullptr;
    cudaGetSymbolAddress(&p, s);
    return (float*)p;
}

extern "C" void kernel_launch(void* const* d_in, const int* in_sizes, int n_in,
                              void* d_out, int out_size)
{
    const float* data  = (const float*)d_in[0];
    const float* ln_g  = (const float*)d_in[1];
    const float* ln_b  = (const float*)d_in[2];
    const float* jq_w  = (const float*)d_in[3];
    const float* jq_b  = (const float*)d_in[4];
    const float* jk_w  = (const float*)d_in[5];
    const float* jk_b  = (const float*)d_in[6];
    const float* jv_w  = (const float*)d_in[7];
    const float* jv_b  = (const float*)d_in[8];
    const float* jbn_g = (const float*)d_in[9];
    const float* jbn_b = (const float*)d_in[10];
    const float* jf1_w = (const float*)d_in[11];
    const float* jf1_b = (const float*)d_in[12];
    const float* jf2_w = (const float*)d_in[13];
    const float* jf2_b = (const float*)d_in[14];
    const float* jfbn_g = (const float*)d_in[15];
    const float* jfbn_b = (const float*)d_in[16];
    // relay-path weights (d_in[17..30]) are dead: relay never feeds back into nodes.

    float* X     = sym_addr(g_X);
    float* embs  = sym_addr(g_embs);
    float* xn    = sym_addr(g_xn);
    float* QKV   = sym_addr(g_QKV);
    float* AKV   = sym_addr(g_AKV);
    float* AKVr  = sym_addr(g_AKVr);
    float* relay0 = sym_addr(g_relay0);
    float* y1    = sym_addr(g_y1);
    float* ret   = sym_addr(g_ret);
    float* H     = sym_addr(g_H);
    float* F     = sym_addr(g_F);
    float* Wj    = sym_addr(g_Wj);
    float* bj    = sym_addr(g_bj);
    float* stats = sym_addr(g_stats);

    prep_kernel<<<(TOTAL + 255) / 256, 256>>>(data, X, embs);
    relay_init_kernel<<<(Nr * Cc + 255) / 256, 256>>>(X, relay0);

    // pack qkv weights for both layers
    for (int ly = 0; ly < 2; ly++) {
        pack3<<<(3 * Cc * Cc + 255) / 256, 256>>>(
            jq_w + (size_t)ly * Cc * Cc, jk_w + (size_t)ly * Cc * Cc,
            jv_w + (size_t)ly * Cc * Cc,
            jq_b + ly * Cc, jk_b + ly * Cc, jv_b + ly * Cc,
            Wj + (size_t)ly * 3 * Cc * Cc, bj + (size_t)ly * 3 * Cc);
    }

    for (int ly = 0; ly < 2; ly++) {
        const float* lg  = ln_g + ly * Cc;
        const float* lb  = ln_b + ly * Cc;
        const float* Wl  = Wj + (size_t)ly * 3 * Cc * Cc;
        const float* bl  = bj + (size_t)ly * 3 * Cc;
        const float* bng = jbn_g + ly * Cc;
        const float* bnb = jbn_b + ly * Cc;
        const float* f1w = jf1_w + (size_t)ly * DIN * Cc;
        const float* f1b = jf1_b + ly * DIN;
        const float* f2w = jf2_w + (size_t)ly * Cc * DIN;
        const float* f2b = jf2_b + ly * Cc;
        const float* fbg = jfbn_g + ly * Cc;
        const float* fbb = jfbn_b + ly * Cc;

        ln_kernel<<<Pp / 8, 256>>>(X, lg, lb, xn, Pp);

        // fused QKV projection: [Pp,768]
        sgemm128<<<dim3(768 / 128, Pp / 128), 256>>>(xn, Wl, bl, nullptr, QKV,
                                                     Pp, 768, Cc, 0);
        // AKe|AVe from embs with packed k,v rows: [Pp,512]
        sgemm128<<<dim3(512 / 128, Pp / 128), 256>>>(embs, Wl + (size_t)Cc * Cc,
                                                     bl + Cc, nullptr, AKV,
                                                     Pp, 512, Cc, 0);
        // AKr|AVr from relay0: [Nr,512]
        sgemm128<<<dim3(512 / 128, Nr / 128), 256>>>(relay0, Wl + (size_t)Cc * Cc,
                                                     bl + Cc, nullptr, AKVr,
                                                     Nr, 512, Cc, 0);

        attn_j<<<Pp, 256>>>(QKV, AKV, AKVr, xn, y1);

        bn_zero<<<2, 256>>>(stats);
        bn_stats<<<Pp / 64, 256>>>(y1, stats, Pp);
        bn_apply<<<(Pp * Cc + 255) / 256, 256>>>(y1, stats, bng, bnb, ret, Pp, 0);

        sgemm128<<<dim3(DIN / 128, Pp / 128), 256>>>(ret, f1w, f1b, nullptr, H,
                                                     Pp, DIN, Cc, 1);
        sgemm128<<<dim3(Cc / 128, Pp / 128), 256>>>(H, f2w, f2b, ret, F,
                                                    Pp, Cc, DIN, 0);

        bn_zero<<<2, 256>>>(stats);
        bn_stats<<<Pp / 64, 256>>>(F, stats, Pp);
        bn_apply<<<(Pp * Cc + 255) / 256, 256>>>(F, stats, fbg, fbb, X, Pp, 1);
    }

    final_kernel<<<(TOTAL + 255) / 256, 256>>>(X, (float*)d_out);
}

// round 8
// speedup vs baseline: 2.8219x; 1.7500x over previous
#include <cuda_runtime.h>
#include <cuda_bf16.h>
#include <math.h>
#include <stdint.h>

// Problem constants
#define Cc 256
#define Vv 17
#define Tt 256
#define Nr 1024            // B*T
#define Pp 17408           // Nr*Vv
#define DIN 1024
#define TOTAL 4456448      // B*C*V*T
#define INV_SQRT_DK 0.17677669529663687f

// 0-indexed adjacency (padded), degrees
__constant__ int c_nbr[17][5] = {
    {0,1,2,5,6},{0,1,3,0,0},{0,2,4,0,0},{1,3,0,0,0},{2,4,0,0,0},
    {0,5,7,11,0},{0,6,8,12,0},{5,7,9,0,0},{6,8,12,0,0},{7,9,0,0,0},
    {8,10,0,0,0},{8,11,13,0,0},{10,12,14,0,0},{11,13,15,0,0},{12,14,16,0,0},
    {13,15,0,0,0},{14,16,0,0,0}
};
__constant__ int c_deg[17] = {5,3,3,2,2,4,4,3,3,2,2,3,3,3,3,2,2};

// fp32 scratch
__device__ float g_X[Pp*Cc];
__device__ float g_xn[Pp*Cc];
__device__ float g_QKV[Pp*3*Cc];
__device__ float g_AKV[Pp*2*Cc];
__device__ float g_AKVr[Nr*2*Cc];
__device__ float g_y1[Pp*Cc];
__device__ float g_ret[Pp*Cc];
__device__ float g_F[Pp*Cc];
__device__ float g_bj[2*3*Cc];
__device__ float g_stats[2*Cc];
// bf16 hi/lo scratch
__device__ __nv_bfloat16 g_Eh[Pp*Cc],  g_El[Pp*Cc];
__device__ __nv_bfloat16 g_Rh[Nr*Cc],  g_Rl[Nr*Cc];
__device__ __nv_bfloat16 g_xnh[Pp*Cc], g_xnl[Pp*Cc];
__device__ __nv_bfloat16 g_reth[Pp*Cc], g_retl[Pp*Cc];
__device__ __nv_bfloat16 g_Hh[Pp*DIN], g_Hl[Pp*DIN];
__device__ __nv_bfloat16 g_Wjh[2*3*Cc*Cc], g_Wjl[2*3*Cc*Cc];
__device__ __nv_bfloat16 g_F1h[2*DIN*Cc], g_F1l[2*DIN*Cc];
__device__ __nv_bfloat16 g_F2h[2*Cc*DIN], g_F2l[2*Cc*DIN];

// ---------------- helpers ----------------
__device__ __forceinline__ uint32_t smem_u32(const void* p) {
    return (uint32_t)__cvta_generic_to_shared(p);
}
__device__ __forceinline__ void cpa16(uint32_t d, const void* s) {
    asm volatile("cp.async.cg.shared.global [%0], [%1], 16;" :: "r"(d), "l"(s));
}
#define CP_COMMIT() asm volatile("cp.async.commit_group;" ::: "memory")
#define CP_WAIT1()  asm volatile("cp.async.wait_group 1;" ::: "memory")
__device__ __forceinline__ void ldsm4(uint32_t* r, uint32_t a) {
    asm volatile("ldmatrix.sync.aligned.m8n8.x4.shared.b16 {%0,%1,%2,%3}, [%4];"
                 : "=r"(r[0]), "=r"(r[1]), "=r"(r[2]), "=r"(r[3]) : "r"(a));
}
__device__ __forceinline__ void mma_bf16(float* c, const uint32_t* a, const uint32_t* b) {
    asm volatile("mma.sync.aligned.m16n8k16.row.col.f32.bf16.bf16.f32 "
                 "{%0,%1,%2,%3}, {%4,%5,%6,%7}, {%8,%9}, {%0,%1,%2,%3};"
                 : "+f"(c[0]), "+f"(c[1]), "+f"(c[2]), "+f"(c[3])
                 : "r"(a[0]), "r"(a[1]), "r"(a[2]), "r"(a[3]), "r"(b[0]), "r"(b[1]));
}
__device__ __forceinline__ void f2hl(float v, __nv_bfloat16& h, __nv_bfloat16& l) {
    h = __float2bfloat16(v);
    l = __float2bfloat16(v - __bfloat162float(h));
}

// ---------------- tensor-core GEMM (mma.sync bf16x3) ----------------
// out = A @ W^T; A[M,K], W[N,K] split hi/lo bf16, K-major. M%128==0, N%128==0, K%32==0.
#define BK 32
#define TSTRIDE 80                    // padded bytes per smem row (conflict-free ldmatrix)
#define TILE_BYTES (128*TSTRIDE)      // 10240
#define STAGE_BYTES (4*TILE_BYTES)    // 40960
#define GEMM_SMEM (2*STAGE_BYTES)     // 81920

__global__ void __launch_bounds__(256) gemm_mma(
    const __nv_bfloat16* __restrict__ Ah, const __nv_bfloat16* __restrict__ Al,
    const __nv_bfloat16* __restrict__ Wh, const __nv_bfloat16* __restrict__ Wl,
    const float* __restrict__ bias, const float* __restrict__ res,
    float* __restrict__ outf,
    __nv_bfloat16* __restrict__ outh, __nv_bfloat16* __restrict__ outl,
    int M, int N, int K, int relu)
{
    extern __shared__ char smem[];
    const uint32_t sb = smem_u32(smem);
    const int tid = threadIdx.x;
    const int warp = tid >> 5, lane = tid & 31;
    const int bm = blockIdx.y * 128;
    const int bn = blockIdx.x * 128;
    const int wm = (warp >> 1) * 32;
    const int wn = (warp & 1) * 64;

    const __nv_bfloat16* srcs[4] = {
        Ah + (size_t)bm * K, Al + (size_t)bm * K,
        Wh + (size_t)bn * K, Wl + (size_t)bn * K
    };

    auto load_stage = [&](int stage, int kc) {
        const uint32_t base = sb + stage * STAGE_BYTES;
        const int k0 = kc * BK;
        #pragma unroll
        for (int t2 = 0; t2 < 4; t2++) {
            const uint32_t tb = base + t2 * TILE_BYTES;
            const __nv_bfloat16* s = srcs[t2] + k0;
            #pragma unroll
            for (int u0 = 0; u0 < 2; u0++) {
                int u = tid + u0 * 256;          // 512 units: 128 rows x 4 16B-chunks
                int row = u >> 2, ch = u & 3;
                cpa16(tb + row * TSTRIDE + ch * 16, s + (size_t)row * K + ch * 8);
            }
        }
    };

    float acc[2][8][4] = {};

    load_stage(0, 0);
    CP_COMMIT();
    const int NCK = K / BK;
    for (int kc = 0; kc < NCK; kc++) {
        if (kc + 1 < NCK) load_stage((kc + 1) & 1, kc + 1);
        CP_COMMIT();
        CP_WAIT1();
        __syncthreads();

        const uint32_t base = sb + (kc & 1) * STAGE_BYTES;
        const uint32_t A_h = base;
        const uint32_t A_l = base + TILE_BYTES;
        const uint32_t W_h = base + 2 * TILE_BYTES;
        const uint32_t W_l = base + 3 * TILE_BYTES;

        #pragma unroll
        for (int fk = 0; fk < 2; fk++) {
            // A fragments (hi & lo) for both 16-row m tiles
            uint32_t ah[2][4], al[2][4];
            {
                int arow = wm + (lane & 15);
                int abyte = fk * 32 + ((lane >> 4) << 4);
                ldsm4(ah[0], A_h + arow * TSTRIDE + abyte);
                ldsm4(ah[1], A_h + (arow + 16) * TSTRIDE + abyte);
                ldsm4(al[0], A_l + arow * TSTRIDE + abyte);
                ldsm4(al[1], A_l + (arow + 16) * TSTRIDE + abyte);
            }
            // B fragments (hi & lo), 8 n-octets
            uint32_t wh[8][2], wl[8][2];
            {
                int brow = wn + ((lane & 16) >> 1) + (lane & 7);
                int bbyte = fk * 32 + (((lane >> 3) & 1) << 4);
                #pragma unroll
                for (int fo = 0; fo < 4; fo++) {
                    uint32_t r[4];
                    ldsm4(r, W_h + (brow + fo * 16) * TSTRIDE + bbyte);
                    wh[2 * fo][0] = r[0]; wh[2 * fo][1] = r[1];
                    wh[2 * fo + 1][0] = r[2]; wh[2 * fo + 1][1] = r[3];
                    ldsm4(r, W_l + (brow + fo * 16) * TSTRIDE + bbyte);
                    wl[2 * fo][0] = r[0]; wl[2 * fo][1] = r[1];
                    wl[2 * fo + 1][0] = r[2]; wl[2 * fo + 1][1] = r[3];
                }
            }
            #pragma unroll
            for (int fm = 0; fm < 2; fm++)
                #pragma unroll
                for (int fn = 0; fn < 8; fn++) {
                    mma_bf16(acc[fm][fn], ah[fm], wh[fn]);   // hi*hi
                    mma_bf16(acc[fm][fn], al[fm], wh[fn]);   // lo*hi
                    mma_bf16(acc[fm][fn], ah[fm], wl[fn]);   // hi*lo
                }
        }
        __syncthreads();
    }

    // ---------------- epilogue ----------------
    #pragma unroll
    for (int fm = 0; fm < 2; fm++) {
        #pragma unroll
        for (int fn = 0; fn < 8; fn++) {
            int r0 = bm + wm + fm * 16 + (lane >> 2);
            int c  = bn + wn + fn * 8 + (lane & 3) * 2;
            #pragma unroll
            for (int half = 0; half < 2; half++) {
                size_t row = (size_t)(r0 + half * 8);
                float v0 = acc[fm][fn][half * 2];
                float v1 = acc[fm][fn][half * 2 + 1];
                if (bias) { v0 += bias[c]; v1 += bias[c + 1]; }
                if (res) {
                    float2 rr = *(const float2*)(res + row * N + c);
                    v0 += rr.x; v1 += rr.y;
                }
                if (relu) { v0 = fmaxf(v0, 0.f); v1 = fmaxf(v1, 0.f); }
                if (outf) *(float2*)(outf + row * N + c) = make_float2(v0, v1);
                if (outh) {
                    __nv_bfloat16 h0, l0, h1, l1;
                    f2hl(v0, h0, l0); f2hl(v1, h1, l1);
                    *(__nv_bfloat162*)(outh + row * N + c) = __nv_bfloat162(h0, h1);
                    *(__nv_bfloat162*)(outl + row * N + c) = __nv_bfloat162(l0, l1);
                }
            }
        }
    }
}

// ---------------- layout / prep ----------------
__global__ void prep_kernel(const float* __restrict__ data, float* __restrict__ X,
                            __nv_bfloat16* __restrict__ Eh, __nv_bfloat16* __restrict__ El)
{
    int idx = blockIdx.x * blockDim.x + threadIdx.x;
    if (idx >= TOTAL) return;
    int t = idx % Tt;
    int v = (idx / Tt) % Vv;
    int c = (idx / (Tt * Vv)) % Cc;
    int b = idx / (Tt * Vv * Cc);
    float val = data[idx];
    size_t o = (size_t)((b * Tt + t) * Vv + v) * Cc + c;
    X[o] = val;
    f2hl(val, Eh[o], El[o]);
}

__global__ void relay_init_kernel(const float* __restrict__ X,
                                  __nv_bfloat16* __restrict__ Rh, __nv_bfloat16* __restrict__ Rl)
{
    int idx = blockIdx.x * blockDim.x + threadIdx.x;
    if (idx >= Nr * Cc) return;
    int n = idx >> 8;
    int c = idx & 255;
    float s = 0.f;
    #pragma unroll
    for (int v = 0; v < Vv; v++) s += X[(size_t)(n * Vv + v) * Cc + c];
    f2hl(s * (1.0f / Vv), Rh[idx], Rl[idx]);
}

__global__ void final_kernel(const float* __restrict__ X, float* __restrict__ out)
{
    int idx = blockIdx.x * blockDim.x + threadIdx.x;
    if (idx >= TOTAL) return;
    int t = idx % Tt;
    int v = (idx / Tt) % Vv;
    int c = (idx / (Tt * Vv)) % Cc;
    int b = idx / (Tt * Vv * Cc);
    out[idx] = X[(size_t)((b * Tt + t) * Vv + v) * Cc + c];
}

// ---------------- weight pack/split ----------------
__global__ void pack3hl(const float* __restrict__ q, const float* __restrict__ k,
                        const float* __restrict__ v,
                        const float* __restrict__ qb, const float* __restrict__ kb,
                        const float* __restrict__ vb,
                        __nv_bfloat16* __restrict__ Whi, __nv_bfloat16* __restrict__ Wlo,
                        float* __restrict__ b)
{
    int idx = blockIdx.x * blockDim.x + threadIdx.x;
    if (idx < 3 * Cc)
        b[idx] = (idx < Cc) ? qb[idx] : (idx < 2 * Cc) ? kb[idx - Cc] : vb[idx - 2 * Cc];
    if (idx >= 3 * Cc * Cc) return;
    int row = idx >> 8;
    int col = idx & 255;
    const float* src = (row < Cc) ? q + (size_t)row * Cc
                     : (row < 2 * Cc) ? k + (size_t)(row - Cc) * Cc
                     : v + (size_t)(row - 2 * Cc) * Cc;
    f2hl(src[col], Whi[idx], Wlo[idx]);
}

__global__ void wsplit(const float* __restrict__ w, __nv_bfloat16* __restrict__ h,
                       __nv_bfloat16* __restrict__ l, int n)
{
    int idx = blockIdx.x * blockDim.x + threadIdx.x;
    if (idx >= n) return;
    f2hl(w[idx], h[idx], l[idx]);
}

// ---------------- LayerNorm ----------------
__global__ void __launch_bounds__(256) ln_kernel(const float* __restrict__ x,
                                                 const float* __restrict__ g,
                                                 const float* __restrict__ b,
                                                 float* __restrict__ y,
                                                 __nv_bfloat16* __restrict__ yh,
                                                 __nv_bfloat16* __restrict__ yl)
{
    int row = blockIdx.x * 8 + (threadIdx.x >> 5);
    int lane = threadIdx.x & 31;
    const float* xr = x + (size_t)row * Cc;
    float v[8];
    float s = 0.f;
    #pragma unroll
    for (int i = 0; i < 8; i++) { v[i] = xr[lane + 32 * i]; s += v[i]; }
    #pragma unroll
    for (int o = 16; o; o >>= 1) s += __shfl_xor_sync(~0u, s, o);
    float mean = s * (1.0f / Cc);
    float s2 = 0.f;
    #pragma unroll
    for (int i = 0; i < 8; i++) { float d = v[i] - mean; s2 += d * d; }
    #pragma unroll
    for (int o = 16; o; o >>= 1) s2 += __shfl_xor_sync(~0u, s2, o);
    float rs = rsqrtf(s2 * (1.0f / Cc) + 1e-6f);
    #pragma unroll
    for (int i = 0; i < 8; i++) {
        int c = lane + 32 * i;
        size_t o = (size_t)row * Cc + c;
        float yv = (v[i] - mean) * rs * g[c] + b[c];
        y[o] = yv;
        f2hl(yv, yh[o], yl[o]);
    }
}

// ---------------- graph attention (7 slots), packed inputs ----------------
__global__ void __launch_bounds__(256) attn_j(const float* __restrict__ QKV,
                                              const float* __restrict__ AKV,
                                              const float* __restrict__ AKVr,
                                              const float* __restrict__ xn,
                                              float* __restrict__ y1)
{
    int p = blockIdx.x;
    int co = threadIdx.x;
    int n = p / Vv, l = p - n * Vv;
    size_t qbase = (size_t)p * 768 + co;
    size_t abase = (size_t)p * 512 + co;
    size_t rbase = (size_t)n * 512 + co;
    float q = QKV[qbase];
    int deg = c_deg[l];
    float sc[7];
    #pragma unroll
    for (int w = 0; w < 5; w++) {
        float d = -1e30f;
        if (w < deg) {
            int j = c_nbr[l][w];
            float dd = q * QKV[(size_t)(n * Vv + j) * 768 + 256 + co];
            #pragma unroll
            for (int o = 16; o; o >>= 1) dd += __shfl_xor_sync(~0u, dd, o);
            d = dd * INV_SQRT_DK;
        }
        sc[w] = d;
    }
    {
        float dd = q * AKV[abase];
        #pragma unroll
        for (int o = 16; o; o >>= 1) dd += __shfl_xor_sync(~0u, dd, o);
        sc[5] = dd * INV_SQRT_DK;
        dd = q * AKVr[rbase];
        #pragma unroll
        for (int o = 16; o; o >>= 1) dd += __shfl_xor_sync(~0u, dd, o);
        sc[6] = dd * INV_SQRT_DK;
    }
    float mx = sc[0];
    #pragma unroll
    for (int w = 1; w < 7; w++) mx = fmaxf(mx, sc[w]);
    float wg[7];
    float sum = 0.f;
    #pragma unroll
    for (int w = 0; w < 7; w++) { wg[w] = expf(sc[w] - mx); sum += wg[w]; }
    float att = 0.f;
    #pragma unroll
    for (int w = 0; w < 5; w++)
        if (w < deg) att += wg[w] * QKV[(size_t)(n * Vv + c_nbr[l][w]) * 768 + 512 + co];
    att += wg[5] * AKV[abase + 256] + wg[6] * AKVr[rbase + 256];
    y1[(size_t)p * Cc + co] = xn[(size_t)p * Cc + co] + att / sum;
}

// ---------------- BatchNorm (axes 0,2) ----------------
__global__ void bn_zero(float* __restrict__ stats)
{
    int i = blockIdx.x * blockDim.x + threadIdx.x;
    if (i < 2 * Cc) stats[i] = 0.f;
}

__global__ void __launch_bounds__(256) bn_stats(const float* __restrict__ x,
                                                float* __restrict__ stats, int rows)
{
    int c = threadIdx.x;
    int r0 = blockIdx.x * 64;
    float s = 0.f, s2 = 0.f;
    for (int r = r0; r < r0 + 64; r++) {
        float v = x[(size_t)r * Cc + c];
        s += v; s2 += v * v;
    }
    atomicAdd(&stats[c], s);
    atomicAdd(&stats[Cc + c], s2);
}

__global__ void __launch_bounds__(256) bn_apply(const float* __restrict__ x,
                                                const float* __restrict__ stats,
                                                const float* __restrict__ g,
                                                const float* __restrict__ b,
                                                float* __restrict__ y,
                                                __nv_bfloat16* __restrict__ yh,
                                                __nv_bfloat16* __restrict__ yl,
                                                int rows, int leaky)
{
    int idx = blockIdx.x * blockDim.x + threadIdx.x;
    if (idx >= rows * Cc) return;
    int c = idx & 255;
    float inv = 1.0f / rows;
    float mean = stats[c] * inv;
    float var = stats[Cc + c] * inv - mean * mean;
    float v = (x[idx] - mean) * rsqrtf(var + 1e-5f) * g[c] + b[c];
    if (leaky) v = v > 0.f ? v : 0.01f * v;
    y[idx] = v;
    if (yh) f2hl(v, yh[idx], yl[idx]);
}

// ---------------- host ----------------
template <typename Sym>
static float* sym_f(const Sym& s) { void* p = nullptr; cudaGetSymbolAddress(&p, s); return (float*)p; }
template <typename Sym>
static __nv_bfloat16* sym_b(const Sym& s) { void* p = nullptr; cudaGetSymbolAddress(&p, s); return (__nv_bfloat16*)p; }

extern "C" void kernel_launch(void* const* d_in, const int* in_sizes, int n_in,
                              void* d_out, int out_size)
{
    const float* data  = (const float*)d_in[0];
    const float* ln_g  = (const float*)d_in[1];
    const float* ln_b  = (const float*)d_in[2];
    const float* jq_w  = (const float*)d_in[3];
    const float* jq_b  = (const float*)d_in[4];
    const float* jk_w  = (const float*)d_in[5];
    const float* jk_b  = (const float*)d_in[6];
    const float* jv_w  = (const float*)d_in[7];
    const float* jv_b  = (const float*)d_in[8];
    const float* jbn_g = (const float*)d_in[9];
    const float* jbn_b = (const float*)d_in[10];
    const float* jf1_w = (const float*)d_in[11];
    const float* jf1_b = (const float*)d_in[12];
    const float* jf2_w = (const float*)d_in[13];
    const float* jf2_b = (const float*)d_in[14];
    const float* jfbn_g = (const float*)d_in[15];
    const float* jfbn_b = (const float*)d_in[16];
    // relay-path weights (d_in[17..30]) are dead: relay never feeds back into nodes.

    float* X    = sym_f(g_X);
    float* xn   = sym_f(g_xn);
    float* QKV  = sym_f(g_QKV);
    float* AKV  = sym_f(g_AKV);
    float* AKVr = sym_f(g_AKVr);
    float* y1   = sym_f(g_y1);
    float* ret  = sym_f(g_ret);
    float* F    = sym_f(g_F);
    float* bj   = sym_f(g_bj);
    float* stats = sym_f(g_stats);
    __nv_bfloat16 *Eh = sym_b(g_Eh), *El = sym_b(g_El);
    __nv_bfloat16 *Rh = sym_b(g_Rh), *Rl = sym_b(g_Rl);
    __nv_bfloat16 *xnh = sym_b(g_xnh), *xnl = sym_b(g_xnl);
    __nv_bfloat16 *reth = sym_b(g_reth), *retl = sym_b(g_retl);
    __nv_bfloat16 *Hh = sym_b(g_Hh), *Hl = sym_b(g_Hl);
    __nv_bfloat16 *Wjh = sym_b(g_Wjh), *Wjl = sym_b(g_Wjl);
    __nv_bfloat16 *F1h = sym_b(g_F1h), *F1l = sym_b(g_F1l);
    __nv_bfloat16 *F2h = sym_b(g_F2h), *F2l = sym_b(g_F2l);

    static bool attr_set = false;
    if (!attr_set) {
        cudaFuncSetAttribute(gemm_mma, cudaFuncAttributeMaxDynamicSharedMemorySize, GEMM_SMEM);
        attr_set = true;
    }

    prep_kernel<<<(TOTAL + 255) / 256, 256>>>(data, X, Eh, El);
    relay_init_kernel<<<(Nr * Cc + 255) / 256, 256>>>(X, Rh, Rl);

    for (int ly = 0; ly < 2; ly++) {
        pack3hl<<<(3 * Cc * Cc + 255) / 256, 256>>>(
            jq_w + (size_t)ly * Cc * Cc, jk_w + (size_t)ly * Cc * Cc,
            jv_w + (size_t)ly * Cc * Cc,
            jq_b + ly * Cc, jk_b + ly * Cc, jv_b + ly * Cc,
            Wjh + (size_t)ly * 3 * Cc * Cc, Wjl + (size_t)ly * 3 * Cc * Cc,
            bj + (size_t)ly * 3 * Cc);
        wsplit<<<(DIN * Cc + 255) / 256, 256>>>(jf1_w + (size_t)ly * DIN * Cc,
                                                F1h + (size_t)ly * DIN * Cc,
                                                F1l + (size_t)ly * DIN * Cc, DIN * Cc);
        wsplit<<<(Cc * DIN + 255) / 256, 256>>>(jf2_w + (size_t)ly * Cc * DIN,
                                                F2h + (size_t)ly * Cc * DIN,
                                                F2l + (size_t)ly * Cc * DIN, Cc * DIN);
    }

    for (int ly = 0; ly < 2; ly++) {
        const float* lg  = ln_g + ly * Cc;
        const float* lb  = ln_b + ly * Cc;
        const __nv_bfloat16* Wh = Wjh + (size_t)ly * 3 * Cc * Cc;
        const __nv_bfloat16* Wl = Wjl + (size_t)ly * 3 * Cc * Cc;
        const float* bl  = bj + (size_t)ly * 3 * Cc;
        const float* bng = jbn_g + ly * Cc;
        const float* bnb = jbn_b + ly * Cc;
        const __nv_bfloat16* f1h = F1h + (size_t)ly * DIN * Cc;
        const __nv_bfloat16* f1l = F1l + (size_t)ly * DIN * Cc;
        const float* f1b = jf1_b + ly * DIN;
        const __nv_bfloat16* f2h = F2h + (size_t)ly * Cc * DIN;
        const __nv_bfloat16* f2l = F2l + (size_t)ly * Cc * DIN;
        const float* f2b = jf2_b + ly * Cc;
        const float* fbg = jfbn_g + ly * Cc;
        const float* fbb = jfbn_b + ly * Cc;

        ln_kernel<<<Pp / 8, 256>>>(X, lg, lb, xn, xnh, xnl);

        // QKV: [Pp,768] = xn @ Wqkv^T
        gemm_mma<<<dim3(768 / 128, Pp / 128), 256, GEMM_SMEM>>>(
            xnh, xnl, Wh, Wl, bl, nullptr, QKV, nullptr, nullptr, Pp, 768, Cc, 0);
        // AKe|AVe: [Pp,512] = embs @ Wkv^T
        gemm_mma<<<dim3(512 / 128, Pp / 128), 256, GEMM_SMEM>>>(
            Eh, El, Wh + (size_t)Cc * Cc, Wl + (size_t)Cc * Cc, bl + Cc, nullptr,
            AKV, nullptr, nullptr, Pp, 512, Cc, 0);
        // AKr|AVr: [Nr,512] = relay0 @ Wkv^T
        gemm_mma<<<dim3(512 / 128, Nr / 128), 256, GEMM_SMEM>>>(
            Rh, Rl, Wh + (size_t)Cc * Cc, Wl + (size_t)Cc * Cc, bl + Cc, nullptr,
            AKVr, nullptr, nullptr, Nr, 512, Cc, 0);

        attn_j<<<Pp, 256>>>(QKV, AKV, AKVr, xn, y1);

        bn_zero<<<2, 256>>>(stats);
        bn_stats<<<Pp / 64, 256>>>(y1, stats, Pp);
        bn_apply<<<(Pp * Cc + 255) / 256, 256>>>(y1, stats, bng, bnb, ret, reth, retl, Pp, 0);

        // FFN1: H = relu(ret @ f1^T + b1), written directly as hi/lo bf16
        gemm_mma<<<dim3(DIN / 128, Pp / 128), 256, GEMM_SMEM>>>(
            reth, retl, f1h, f1l, f1b, nullptr, nullptr, Hh, Hl, Pp, DIN, Cc, 1);
        // FFN2: F = H @ f2^T + b2 + ret
        gemm_mma<<<dim3(Cc / 128, Pp / 128), 256, GEMM_SMEM>>>(
            Hh, Hl, f2h, f2l, f2b, ret, F, nullptr, nullptr, Pp, Cc, DIN, 0);

        bn_zero<<<2, 256>>>(stats);
        bn_stats<<<Pp / 64, 256>>>(F, stats, Pp);
        bn_apply<<<(Pp * Cc + 255) / 256, 256>>>(F, stats, fbg, fbb, X, nullptr, nullptr, Pp, 1);
    }

    final_kernel<<<(TOTAL + 255) / 256, 256>>>(X, (float*)d_out);
}

// round 9
// speedup vs baseline: 2.9283x; 1.0377x over previous
#include <cuda_runtime.h>
#include <cuda_bf16.h>
#include <math.h>
#include <stdint.h>

// Problem constants
#define Cc 256
#define Vv 17
#define Tt 256
#define Nr 1024            // B*T
#define Pp 17408           // Nr*Vv
#define DIN 1024
#define TOTAL 4456448      // B*C*V*T
#define INV_SQRT_DK 0.17677669529663687f

// 0-indexed adjacency (padded), degrees
__constant__ int c_nbr[17][5] = {
    {0,1,2,5,6},{0,1,3,0,0},{0,2,4,0,0},{1,3,0,0,0},{2,4,0,0,0},
    {0,5,7,11,0},{0,6,8,12,0},{5,7,9,0,0},{6,8,12,0,0},{7,9,0,0,0},
    {8,10,0,0,0},{8,11,13,0,0},{10,12,14,0,0},{11,13,15,0,0},{12,14,16,0,0},
    {13,15,0,0,0},{14,16,0,0,0}
};
__constant__ int c_deg[17] = {5,3,3,2,2,4,4,3,3,2,2,3,3,3,3,2,2};

// fp32 scratch
__device__ float g_X[Pp*Cc];
__device__ float g_xn[Pp*Cc];
__device__ float g_QKV[Pp*3*Cc];
__device__ float g_AKV[Pp*2*Cc];
__device__ float g_AKVr[Nr*2*Cc];
__device__ float g_y1[Pp*Cc];
__device__ float g_ret[Pp*Cc];
__device__ float g_F[Pp*Cc];
__device__ float g_bj[2*3*Cc];
__device__ float g_stats[2*Cc];
// bf16 hi/lo scratch
__device__ __nv_bfloat16 g_Eh[Pp*Cc],  g_El[Pp*Cc];
__device__ __nv_bfloat16 g_Rh[Nr*Cc],  g_Rl[Nr*Cc];
__device__ __nv_bfloat16 g_xnh[Pp*Cc], g_xnl[Pp*Cc];
__device__ __nv_bfloat16 g_reth[Pp*Cc], g_retl[Pp*Cc];
__device__ __nv_bfloat16 g_Hh[Pp*DIN], g_Hl[Pp*DIN];
__device__ __nv_bfloat16 g_Wjh[2*3*Cc*Cc], g_Wjl[2*3*Cc*Cc];
__device__ __nv_bfloat16 g_F1h[2*DIN*Cc], g_F1l[2*DIN*Cc];
__device__ __nv_bfloat16 g_F2h[2*Cc*DIN], g_F2l[2*Cc*DIN];

// ---------------- helpers ----------------
__device__ __forceinline__ uint32_t smem_u32(const void* p) {
    return (uint32_t)__cvta_generic_to_shared(p);
}
__device__ __forceinline__ void cpa16(uint32_t d, const void* s) {
    asm volatile("cp.async.cg.shared.global [%0], [%1], 16;" :: "r"(d), "l"(s));
}
#define CP_COMMIT() asm volatile("cp.async.commit_group;" ::: "memory")
#define CP_WAIT1()  asm volatile("cp.async.wait_group 1;" ::: "memory")
__device__ __forceinline__ void ldsm4(uint32_t* r, uint32_t a) {
    asm volatile("ldmatrix.sync.aligned.m8n8.x4.shared.b16 {%0,%1,%2,%3}, [%4];"
                 : "=r"(r[0]), "=r"(r[1]), "=r"(r[2]), "=r"(r[3]) : "r"(a));
}
__device__ __forceinline__ void mma_bf16(float* c, const uint32_t* a, const uint32_t* b) {
    asm volatile("mma.sync.aligned.m16n8k16.row.col.f32.bf16.bf16.f32 "
                 "{%0,%1,%2,%3}, {%4,%5,%6,%7}, {%8,%9}, {%0,%1,%2,%3};"
                 : "+f"(c[0]), "+f"(c[1]), "+f"(c[2]), "+f"(c[3])
                 : "r"(a[0]), "r"(a[1]), "r"(a[2]), "r"(a[3]), "r"(b[0]), "r"(b[1]));
}
__device__ __forceinline__ void f2hl(float v, __nv_bfloat16& h, __nv_bfloat16& l) {
    h = __float2bfloat16(v);
    l = __float2bfloat16(v - __bfloat162float(h));
}

// ---------------- tensor-core GEMM (mma.sync bf16x3), 3-stage pipeline ----------------
// out = A @ W^T; A[M,K], W[N,K] split hi/lo bf16, K-major. M%128==0, N%128==0, K%32==0.
#define BK 32
#define TSTRIDE 80                    // padded bytes per smem row (conflict-free ldmatrix)
#define TILE_BYTES (128*TSTRIDE)      // 10240
#define STAGE_BYTES (4*TILE_BYTES)    // 40960
#define NSTAGE 3
#define GEMM_SMEM (NSTAGE*STAGE_BYTES) // 122880

__global__ void __launch_bounds__(256) gemm_mma(
    const __nv_bfloat16* __restrict__ Ah, const __nv_bfloat16* __restrict__ Al,
    const __nv_bfloat16* __restrict__ Wh, const __nv_bfloat16* __restrict__ Wl,
    const float* __restrict__ bias, const float* __restrict__ res,
    float* __restrict__ outf,
    __nv_bfloat16* __restrict__ outh, __nv_bfloat16* __restrict__ outl,
    int M, int N, int K, int relu)
{
    extern __shared__ char smem[];
    const uint32_t sb = smem_u32(smem);
    const int tid = threadIdx.x;
    const int warp = tid >> 5, lane = tid & 31;
    const int bm = blockIdx.y * 128;
    const int bn = blockIdx.x * 128;
    const int wm = (warp >> 1) * 32;
    const int wn = (warp & 1) * 64;

    const __nv_bfloat16* srcs[4] = {
        Ah + (size_t)bm * K, Al + (size_t)bm * K,
        Wh + (size_t)bn * K, Wl + (size_t)bn * K
    };

    auto load_stage = [&](int stage, int kc) {
        const uint32_t base = sb + stage * STAGE_BYTES;
        const int k0 = kc * BK;
        #pragma unroll
        for (int t2 = 0; t2 < 4; t2++) {
            const uint32_t tb = base + t2 * TILE_BYTES;
            const __nv_bfloat16* s = srcs[t2] + k0;
            #pragma unroll
            for (int u0 = 0; u0 < 2; u0++) {
                int u = tid + u0 * 256;          // 512 units: 128 rows x 4 16B-chunks
                int row = u >> 2, ch = u & 3;
                cpa16(tb + row * TSTRIDE + ch * 16, s + (size_t)row * K + ch * 8);
            }
        }
    };

    float acc[2][8][4] = {};
    const int NCK = K / BK;

    load_stage(0, 0);
    CP_COMMIT();
    if (NCK > 1) load_stage(1, 1);
    CP_COMMIT();

    int stage = 0;
    for (int kc = 0; kc < NCK; kc++) {
        CP_WAIT1();                // stage kc resident
        __syncthreads();           // everyone done with stage (kc-1+NSTAGE)%NSTAGE

        // prefetch kc+2 into the freed stage
        int nst = stage + 2; if (nst >= NSTAGE) nst -= NSTAGE;
        if (kc + 2 < NCK) load_stage(nst, kc + 2);
        CP_COMMIT();

        const uint32_t base = sb + stage * STAGE_BYTES;
        const uint32_t A_h = base;
        const uint32_t A_l = base + TILE_BYTES;
        const uint32_t W_h = base + 2 * TILE_BYTES;
        const uint32_t W_l = base + 3 * TILE_BYTES;

        #pragma unroll
        for (int fk = 0; fk < 2; fk++) {
            uint32_t ah[2][4], al[2][4];
            {
                int arow = wm + (lane & 15);
                int abyte = fk * 32 + ((lane >> 4) << 4);
                ldsm4(ah[0], A_h + arow * TSTRIDE + abyte);
                ldsm4(ah[1], A_h + (arow + 16) * TSTRIDE + abyte);
                ldsm4(al[0], A_l + arow * TSTRIDE + abyte);
                ldsm4(al[1], A_l + (arow + 16) * TSTRIDE + abyte);
            }
            uint32_t wh[8][2], wl[8][2];
            {
                int brow = wn + ((lane & 16) >> 1) + (lane & 7);
                int bbyte = fk * 32 + (((lane >> 3) & 1) << 4);
                #pragma unroll
                for (int fo = 0; fo < 4; fo++) {
                    uint32_t r[4];
                    ldsm4(r, W_h + (brow + fo * 16) * TSTRIDE + bbyte);
                    wh[2 * fo][0] = r[0]; wh[2 * fo][1] = r[1];
                    wh[2 * fo + 1][0] = r[2]; wh[2 * fo + 1][1] = r[3];
                    ldsm4(r, W_l + (brow + fo * 16) * TSTRIDE + bbyte);
                    wl[2 * fo][0] = r[0]; wl[2 * fo][1] = r[1];
                    wl[2 * fo + 1][0] = r[2]; wl[2 * fo + 1][1] = r[3];
                }
            }
            #pragma unroll
            for (int fm = 0; fm < 2; fm++)
                #pragma unroll
                for (int fn = 0; fn < 8; fn++) {
                    mma_bf16(acc[fm][fn], ah[fm], wh[fn]);   // hi*hi
                    mma_bf16(acc[fm][fn], al[fm], wh[fn]);   // lo*hi
                    mma_bf16(acc[fm][fn], ah[fm], wl[fn]);   // hi*lo
                }
        }
        stage++; if (stage >= NSTAGE) stage = 0;
    }

    // ---------------- epilogue ----------------
    #pragma unroll
    for (int fm = 0; fm < 2; fm++) {
        #pragma unroll
        for (int fn = 0; fn < 8; fn++) {
            int r0 = bm + wm + fm * 16 + (lane >> 2);
            int c  = bn + wn + fn * 8 + (lane & 3) * 2;
            #pragma unroll
            for (int half = 0; half < 2; half++) {
                size_t row = (size_t)(r0 + half * 8);
                float v0 = acc[fm][fn][half * 2];
                float v1 = acc[fm][fn][half * 2 + 1];
                if (bias) { v0 += bias[c]; v1 += bias[c + 1]; }
                if (res) {
                    float2 rr = *(const float2*)(res + row * N + c);
                    v0 += rr.x; v1 += rr.y;
                }
                if (relu) { v0 = fmaxf(v0, 0.f); v1 = fmaxf(v1, 0.f); }
                if (outf) *(float2*)(outf + row * N + c) = make_float2(v0, v1);
                if (outh) {
                    __nv_bfloat16 h0, l0, h1, l1;
                    f2hl(v0, h0, l0); f2hl(v1, h1, l1);
                    *(__nv_bfloat162*)(outh + row * N + c) = __nv_bfloat162(h0, h1);
                    *(__nv_bfloat162*)(outl + row * N + c) = __nv_bfloat162(l0, l1);
                }
            }
        }
    }
}

// ---------------- layout / prep ----------------
__global__ void prep_kernel(const float* __restrict__ data, float* __restrict__ X,
                            __nv_bfloat16* __restrict__ Eh, __nv_bfloat16* __restrict__ El)
{
    int idx = blockIdx.x * blockDim.x + threadIdx.x;
    if (idx >= TOTAL) return;
    int t = idx % Tt;
    int v = (idx / Tt) % Vv;
    int c = (idx / (Tt * Vv)) % Cc;
    int b = idx / (Tt * Vv * Cc);
    float val = data[idx];
    size_t o = (size_t)((b * Tt + t) * Vv + v) * Cc + c;
    X[o] = val;
    f2hl(val, Eh[o], El[o]);
}

__global__ void relay_init_kernel(const float* __restrict__ X,
                                  __nv_bfloat16* __restrict__ Rh, __nv_bfloat16* __restrict__ Rl)
{
    int idx = blockIdx.x * blockDim.x + threadIdx.x;
    if (idx >= Nr * Cc) return;
    int n = idx >> 8;
    int c = idx & 255;
    float s = 0.f;
    #pragma unroll
    for (int v = 0; v < Vv; v++) s += X[(size_t)(n * Vv + v) * Cc + c];
    f2hl(s * (1.0f / Vv), Rh[idx], Rl[idx]);
}

__global__ void final_kernel(const float* __restrict__ X, float* __restrict__ out)
{
    int idx = blockIdx.x * blockDim.x + threadIdx.x;
    if (idx >= TOTAL) return;
    int t = idx % Tt;
    int v = (idx / Tt) % Vv;
    int c = (idx / (Tt * Vv)) % Cc;
    int b = idx / (Tt * Vv * Cc);
    out[idx] = X[(size_t)((b * Tt + t) * Vv + v) * Cc + c];
}

// ---------------- merged weight prep (one launch per layer) ----------------
// region 0: [0, 196608)            packed qkv hi/lo (+ bias for idx<768)
// region 1: [196608, 458752)       f1 split
// region 2: [458752, 720896)       f2 split
#define WPREP_TOTAL 720896
__global__ void wprep(const float* __restrict__ q, const float* __restrict__ k,
                      const float* __restrict__ v,
                      const float* __restrict__ qb, const float* __restrict__ kb,
                      const float* __restrict__ vb,
                      const float* __restrict__ f1, const float* __restrict__ f2,
                      __nv_bfloat16* __restrict__ Whi, __nv_bfloat16* __restrict__ Wlo,
                      float* __restrict__ b,
                      __nv_bfloat16* __restrict__ F1hi, __nv_bfloat16* __restrict__ F1lo,
                      __nv_bfloat16* __restrict__ F2hi, __nv_bfloat16* __restrict__ F2lo)
{
    int idx = blockIdx.x * blockDim.x + threadIdx.x;
    if (idx >= WPREP_TOTAL) return;
    if (idx < 3 * Cc)
        b[idx] = (idx < Cc) ? qb[idx] : (idx < 2 * Cc) ? kb[idx - Cc] : vb[idx - 2 * Cc];
    if (idx < 3 * Cc * Cc) {
        int row = idx >> 8;
        int col = idx & 255;
        const float* src = (row < Cc) ? q + (size_t)row * Cc
                         : (row < 2 * Cc) ? k + (size_t)(row - Cc) * Cc
                         : v + (size_t)(row - 2 * Cc) * Cc;
        f2hl(src[col], Whi[idx], Wlo[idx]);
    } else if (idx < 3 * Cc * Cc + DIN * Cc) {
        int i = idx - 3 * Cc * Cc;
        f2hl(f1[i], F1hi[i], F1lo[i]);
    } else {
        int i = idx - 3 * Cc * Cc - DIN * Cc;
        f2hl(f2[i], F2hi[i], F2lo[i]);
    }
}

// ---------------- LayerNorm ----------------
__global__ void __launch_bounds__(256) ln_kernel(const float* __restrict__ x,
                                                 const float* __restrict__ g,
                                                 const float* __restrict__ b,
                                                 float* __restrict__ y,
                                                 __nv_bfloat16* __restrict__ yh,
                                                 __nv_bfloat16* __restrict__ yl)
{
    int row = blockIdx.x * 8 + (threadIdx.x >> 5);
    int lane = threadIdx.x & 31;
    const float* xr = x + (size_t)row * Cc;
    float v[8];
    float s = 0.f;
    #pragma unroll
    for (int i = 0; i < 8; i++) { v[i] = xr[lane + 32 * i]; s += v[i]; }
    #pragma unroll
    for (int o = 16; o; o >>= 1) s += __shfl_xor_sync(~0u, s, o);
    float mean = s * (1.0f / Cc);
    float s2 = 0.f;
    #pragma unroll
    for (int i = 0; i < 8; i++) { float d = v[i] - mean; s2 += d * d; }
    #pragma unroll
    for (int o = 16; o; o >>= 1) s2 += __shfl_xor_sync(~0u, s2, o);
    float rs = rsqrtf(s2 * (1.0f / Cc) + 1e-6f);
    #pragma unroll
    for (int i = 0; i < 8; i++) {
        int c = lane + 32 * i;
        size_t o = (size_t)row * Cc + c;
        float yv = (v[i] - mean) * rs * g[c] + b[c];
        y[o] = yv;
        f2hl(yv, yh[o], yl[o]);
    }
}

// ---------------- graph attention (7 slots), packed inputs ----------------
__global__ void __launch_bounds__(256) attn_j(const float* __restrict__ QKV,
                                              const float* __restrict__ AKV,
                                              const float* __restrict__ AKVr,
                                              const float* __restrict__ xn,
                                              float* __restrict__ y1)
{
    int p = blockIdx.x;
    int co = threadIdx.x;
    int n = p / Vv, l = p - n * Vv;
    size_t qbase = (size_t)p * 768 + co;
    size_t abase = (size_t)p * 512 + co;
    size_t rbase = (size_t)n * 512 + co;
    float q = QKV[qbase];
    int deg = c_deg[l];
    float sc[7];
    #pragma unroll
    for (int w = 0; w < 5; w++) {
        float d = -1e30f;
        if (w < deg) {
            int j = c_nbr[l][w];
            float dd = q * QKV[(size_t)(n * Vv + j) * 768 + 256 + co];
            #pragma unroll
            for (int o = 16; o; o >>= 1) dd += __shfl_xor_sync(~0u, dd, o);
            d = dd * INV_SQRT_DK;
        }
        sc[w] = d;
    }
    {
        float dd = q * AKV[abase];
        #pragma unroll
        for (int o = 16; o; o >>= 1) dd += __shfl_xor_sync(~0u, dd, o);
        sc[5] = dd * INV_SQRT_DK;
        dd = q * AKVr[rbase];
        #pragma unroll
        for (int o = 16; o; o >>= 1) dd += __shfl_xor_sync(~0u, dd, o);
        sc[6] = dd * INV_SQRT_DK;
    }
    float mx = sc[0];
    #pragma unroll
    for (int w = 1; w < 7; w++) mx = fmaxf(mx, sc[w]);
    float wg[7];
    float sum = 0.f;
    #pragma unroll
    for (int w = 0; w < 7; w++) { wg[w] = expf(sc[w] - mx); sum += wg[w]; }
    float att = 0.f;
    #pragma unroll
    for (int w = 0; w < 5; w++)
        if (w < deg) att += wg[w] * QKV[(size_t)(n * Vv + c_nbr[l][w]) * 768 + 512 + co];
    att += wg[5] * AKV[abase + 256] + wg[6] * AKVr[rbase + 256];
    y1[(size_t)p * Cc + co] = xn[(size_t)p * Cc + co] + att / sum;
}

// ---------------- BatchNorm (axes 0,2) ----------------
__global__ void bn_zero(float* __restrict__ stats)
{
    int i = blockIdx.x * blockDim.x + threadIdx.x;
    if (i < 2 * Cc) stats[i] = 0.f;
}

__global__ void __launch_bounds__(256) bn_stats(const float* __restrict__ x,
                                                float* __restrict__ stats, int rows)
{
    int c = threadIdx.x;
    int r0 = blockIdx.x * 64;
    float s = 0.f, s2 = 0.f;
    for (int r = r0; r < r0 + 64; r++) {
        float v = x[(size_t)r * Cc + c];
        s += v; s2 += v * v;
    }
    atomicAdd(&stats[c], s);
    atomicAdd(&stats[Cc + c], s2);
}

__global__ void __launch_bounds__(256) bn_apply(const float* __restrict__ x,
                                                const float* __restrict__ stats,
                                                const float* __restrict__ g,
                                                const float* __restrict__ b,
                                                float* __restrict__ y,
                                                __nv_bfloat16* __restrict__ yh,
                                                __nv_bfloat16* __restrict__ yl,
                                                int rows, int leaky)
{
    int idx = blockIdx.x * blockDim.x + threadIdx.x;
    if (idx >= rows * Cc) return;
    int c = idx & 255;
    float inv = 1.0f / rows;
    float mean = stats[c] * inv;
    float var = stats[Cc + c] * inv - mean * mean;
    float v = (x[idx] - mean) * rsqrtf(var + 1e-5f) * g[c] + b[c];
    if (leaky) v = v > 0.f ? v : 0.01f * v;
    y[idx] = v;
    if (yh) f2hl(v, yh[idx], yl[idx]);
}

// ---------------- host ----------------
template <typename Sym>
static float* sym_f(const Sym& s) { void* p = nullptr; cudaGetSymbolAddress(&p, s); return (float*)p; }
template <typename Sym>
static __nv_bfloat16* sym_b(const Sym& s) { void* p = nullptr; cudaGetSymbolAddress(&p, s); return (__nv_bfloat16*)p; }

extern "C" void kernel_launch(void* const* d_in, const int* in_sizes, int n_in,
                              void* d_out, int out_size)
{
    const float* data  = (const float*)d_in[0];
    const float* ln_g  = (const float*)d_in[1];
    const float* ln_b  = (const float*)d_in[2];
    const float* jq_w  = (const float*)d_in[3];
    const float* jq_b  = (const float*)d_in[4];
    const float* jk_w  = (const float*)d_in[5];
    const float* jk_b  = (const float*)d_in[6];
    const float* jv_w  = (const float*)d_in[7];
    const float* jv_b  = (const float*)d_in[8];
    const float* jbn_g = (const float*)d_in[9];
    const float* jbn_b = (const float*)d_in[10];
    const float* jf1_w = (const float*)d_in[11];
    const float* jf1_b = (const float*)d_in[12];
    const float* jf2_w = (const float*)d_in[13];
    const float* jf2_b = (const float*)d_in[14];
    const float* jfbn_g = (const float*)d_in[15];
    const float* jfbn_b = (const float*)d_in[16];
    // relay-path weights (d_in[17..30]) are dead: relay never feeds back into nodes.

    float* X    = sym_f(g_X);
    float* xn   = sym_f(g_xn);
    float* QKV  = sym_f(g_QKV);
    float* AKV  = sym_f(g_AKV);
    float* AKVr = sym_f(g_AKVr);
    float* y1   = sym_f(g_y1);
    float* ret  = sym_f(g_ret);
    float* F    = sym_f(g_F);
    float* bj   = sym_f(g_bj);
    float* stats = sym_f(g_stats);
    __nv_bfloat16 *Eh = sym_b(g_Eh), *El = sym_b(g_El);
    __nv_bfloat16 *Rh = sym_b(g_Rh), *Rl = sym_b(g_Rl);
    __nv_bfloat16 *xnh = sym_b(g_xnh), *xnl = sym_b(g_xnl);
    __nv_bfloat16 *reth = sym_b(g_reth), *retl = sym_b(g_retl);
    __nv_bfloat16 *Hh = sym_b(g_Hh), *Hl = sym_b(g_Hl);
    __nv_bfloat16 *Wjh = sym_b(g_Wjh), *Wjl = sym_b(g_Wjl);
    __nv_bfloat16 *F1h = sym_b(g_F1h), *F1l = sym_b(g_F1l);
    __nv_bfloat16 *F2h = sym_b(g_F2h), *F2l = sym_b(g_F2l);

    static bool attr_set = false;
    if (!attr_set) {
        cudaFuncSetAttribute(gemm_mma, cudaFuncAttributeMaxDynamicSharedMemorySize, GEMM_SMEM);
        attr_set = true;
    }

    prep_kernel<<<(TOTAL + 255) / 256, 256>>>(data, X, Eh, El);
    relay_init_kernel<<<(Nr * Cc + 255) / 256, 256>>>(X, Rh, Rl);

    for (int ly = 0; ly < 2; ly++) {
        wprep<<<(WPREP_TOTAL + 255) / 256, 256>>>(
            jq_w + (size_t)ly * Cc * Cc, jk_w + (size_t)ly * Cc * Cc,
            jv_w + (size_t)ly * Cc * Cc,
            jq_b + ly * Cc, jk_b + ly * Cc, jv_b + ly * Cc,
            jf1_w + (size_t)ly * DIN * Cc, jf2_w + (size_t)ly * Cc * DIN,
            Wjh + (size_t)ly * 3 * Cc * Cc, Wjl + (size_t)ly * 3 * Cc * Cc,
            bj + (size_t)ly * 3 * Cc,
            F1h + (size_t)ly * DIN * Cc, F1l + (size_t)ly * DIN * Cc,
            F2h + (size_t)ly * Cc * DIN, F2l + (size_t)ly * Cc * DIN);
    }

    for (int ly = 0; ly < 2; ly++) {
        const float* lg  = ln_g + ly * Cc;
        const float* lb  = ln_b + ly * Cc;
        const __nv_bfloat16* Wh = Wjh + (size_t)ly * 3 * Cc * Cc;
        const __nv_bfloat16* Wl = Wjl + (size_t)ly * 3 * Cc * Cc;
        const float* bl  = bj + (size_t)ly * 3 * Cc;
        const float* bng = jbn_g + ly * Cc;
        const float* bnb = jbn_b + ly * Cc;
        const __nv_bfloat16* f1h = F1h + (size_t)ly * DIN * Cc;
        const __nv_bfloat16* f1l = F1l + (size_t)ly * DIN * Cc;
        const float* f1b = jf1_b + ly * DIN;
        const __nv_bfloat16* f2h = F2h + (size_t)ly * Cc * DIN;
        const __nv_bfloat16* f2l = F2l + (size_t)ly * Cc * DIN;
        const float* f2b = jf2_b + ly * Cc;
        const float* fbg = jfbn_g + ly * Cc;
        const float* fbb = jfbn_b + ly * Cc;

        ln_kernel<<<Pp / 8, 256>>>(X, lg, lb, xn, xnh, xnl);

        // QKV: [Pp,768] = xn @ Wqkv^T
        gemm_mma<<<dim3(768 / 128, Pp / 128), 256, GEMM_SMEM>>>(
            xnh, xnl, Wh, Wl, bl, nullptr, QKV, nullptr, nullptr, Pp, 768, Cc, 0);
        // AKe|AVe: [Pp,512] = embs @ Wkv^T
        gemm_mma<<<dim3(512 / 128, Pp / 128), 256, GEMM_SMEM>>>(
            Eh, El, Wh + (size_t)Cc * Cc, Wl + (size_t)Cc * Cc, bl + Cc, nullptr,
            AKV, nullptr, nullptr, Pp, 512, Cc, 0);
        // AKr|AVr: [Nr,512] = relay0 @ Wkv^T
        gemm_mma<<<dim3(512 / 128, Nr / 128), 256, GEMM_SMEM>>>(
            Rh, Rl, Wh + (size_t)Cc * Cc, Wl + (size_t)Cc * Cc, bl + Cc, nullptr,
            AKVr, nullptr, nullptr, Nr, 512, Cc, 0);

        attn_j<<<Pp, 256>>>(QKV, AKV, AKVr, xn, y1);

        bn_zero<<<2, 256>>>(stats);
        bn_stats<<<Pp / 64, 256>>>(y1, stats, Pp);
        bn_apply<<<(Pp * Cc + 255) / 256, 256>>>(y1, stats, bng, bnb, ret, reth, retl, Pp, 0);

        // FFN1: H = relu(ret @ f1^T + b1), written directly as hi/lo bf16
        gemm_mma<<<dim3(DIN / 128, Pp / 128), 256, GEMM_SMEM>>>(
            reth, retl, f1h, f1l, f1b, nullptr, nullptr, Hh, Hl, Pp, DIN, Cc, 1);
        // FFN2: F = H @ f2^T + b2 + ret
        gemm_mma<<<dim3(Cc / 128, Pp / 128), 256, GEMM_SMEM>>>(
            Hh, Hl, f2h, f2l, f2b, ret, F, nullptr, nullptr, Pp, Cc, DIN, 0);

        bn_zero<<<2, 256>>>(stats);
        bn_stats<<<Pp / 64, 256>>>(F, stats, Pp);
        bn_apply<<<(Pp * Cc + 255) / 256, 256>>>(F, stats, fbg, fbb, X, nullptr, nullptr, Pp, 1);
    }

    final_kernel<<<(TOTAL + 255) / 256, 256>>>(X, (float*)d_out);
}

// round 10
// speedup vs baseline: 3.4849x; 1.1901x over previous
#include <cuda_runtime.h>
#include <cuda_fp16.h>
#include <math.h>
#include <stdint.h>

// Problem constants
#define Cc 256
#define Vv 17
#define Tt 256
#define Nr 1024            // B*T
#define Pp 17408           // Nr*Vv
#define DIN 1024
#define TOTAL 4456448      // B*C*V*T
#define INV_SQRT_DK 0.17677669529663687f

// 0-indexed adjacency (padded), degrees
__constant__ int c_nbr[17][5] = {
    {0,1,2,5,6},{0,1,3,0,0},{0,2,4,0,0},{1,3,0,0,0},{2,4,0,0,0},
    {0,5,7,11,0},{0,6,8,12,0},{5,7,9,0,0},{6,8,12,0,0},{7,9,0,0,0},
    {8,10,0,0,0},{8,11,13,0,0},{10,12,14,0,0},{11,13,15,0,0},{12,14,16,0,0},
    {13,15,0,0,0},{14,16,0,0,0}
};
__constant__ int c_deg[17] = {5,3,3,2,2,4,4,3,3,2,2,3,3,3,3,2,2};

// fp32 scratch
__device__ float g_X[Pp*Cc];
__device__ float g_xn[Pp*Cc];
__device__ float g_QKV[Pp*3*Cc];
__device__ float g_AKV[Pp*2*Cc];
__device__ float g_AKVr[Nr*2*Cc];
__device__ float g_y1[Pp*Cc];
__device__ float g_ret[Pp*Cc];
__device__ float g_F[Pp*Cc];
__device__ float g_bj[2*3*Cc];
__device__ float g_stats[2*Cc];
// fp16 hi/lo activation scratch (A operands) + fp16 weights (W operands)
__device__ __half g_Eh[Pp*Cc],  g_El[Pp*Cc];
__device__ __half g_Rh[Nr*Cc],  g_Rl[Nr*Cc];
__device__ __half g_xnh[Pp*Cc], g_xnl[Pp*Cc];
__device__ __half g_reth[Pp*Cc], g_retl[Pp*Cc];
__device__ __half g_Hh[Pp*DIN], g_Hl[Pp*DIN];
__device__ __half g_Wj[2*3*Cc*Cc];
__device__ __half g_F1[2*DIN*Cc];
__device__ __half g_F2[2*Cc*DIN];

// ---------------- helpers ----------------
__device__ __forceinline__ uint32_t smem_u32(const void* p) {
    return (uint32_t)__cvta_generic_to_shared(p);
}
__device__ __forceinline__ void cpa16(uint32_t d, const void* s) {
    asm volatile("cp.async.cg.shared.global [%0], [%1], 16;" :: "r"(d), "l"(s));
}
#define CP_COMMIT() asm volatile("cp.async.commit_group;" ::: "memory")
#define CP_WAIT2()  asm volatile("cp.async.wait_group 2;" ::: "memory")
__device__ __forceinline__ void ldsm4(uint32_t* r, uint32_t a) {
    asm volatile("ldmatrix.sync.aligned.m8n8.x4.shared.b16 {%0,%1,%2,%3}, [%4];"
                 : "=r"(r[0]), "=r"(r[1]), "=r"(r[2]), "=r"(r[3]) : "r"(a));
}
__device__ __forceinline__ void mma_f16(float* c, const uint32_t* a, const uint32_t* b) {
    asm volatile("mma.sync.aligned.m16n8k16.row.col.f32.f16.f16.f32 "
                 "{%0,%1,%2,%3}, {%4,%5,%6,%7}, {%8,%9}, {%0,%1,%2,%3};"
                 : "+f"(c[0]), "+f"(c[1]), "+f"(c[2]), "+f"(c[3])
                 : "r"(a[0]), "r"(a[1]), "r"(a[2]), "r"(a[3]), "r"(b[0]), "r"(b[1]));
}
__device__ __forceinline__ void f2hl(float v, __half& h, __half& l) {
    h = __float2half_rn(v);
    l = __float2half_rn(v - __half2float(h));
}

// ---------------- tensor-core GEMM (mma.sync fp16x2), 4-stage pipeline ----------------
// out = A @ W^T; A[M,K] split hi/lo fp16, W[N,K] fp16, K-major.
// M%128==0, N%128==0, K%32==0.
#define BK 32
#define TSTRIDE 80                      // padded bytes per smem row (conflict-free ldmatrix)
#define TILE_BYTES (128*TSTRIDE)        // 10240
#define STAGE_BYTES (3*TILE_BYTES)      // 30720
#define NSTAGE 4
#define GEMM_SMEM (NSTAGE*STAGE_BYTES)  // 122880

__global__ void __launch_bounds__(256) gemm_mma(
    const __half* __restrict__ Ah, const __half* __restrict__ Al,
    const __half* __restrict__ W,
    const float* __restrict__ bias, const float* __restrict__ res,
    float* __restrict__ outf,
    __half* __restrict__ outh, __half* __restrict__ outl,
    int M, int N, int K, int relu)
{
    extern __shared__ char smem[];
    const uint32_t sb = smem_u32(smem);
    const int tid = threadIdx.x;
    const int warp = tid >> 5, lane = tid & 31;
    const int bm = blockIdx.y * 128;
    const int bn = blockIdx.x * 128;
    const int wm = (warp >> 1) * 32;
    const int wn = (warp & 1) * 64;

    const __half* srcs[3] = {
        Ah + (size_t)bm * K, Al + (size_t)bm * K, W + (size_t)bn * K
    };

    auto load_stage = [&](int stage, int kc) {
        const uint32_t base = sb + stage * STAGE_BYTES;
        const int k0 = kc * BK;
        #pragma unroll
        for (int t2 = 0; t2 < 3; t2++) {
            const uint32_t tb = base + t2 * TILE_BYTES;
            const __half* s = srcs[t2] + k0;
            #pragma unroll
            for (int u0 = 0; u0 < 2; u0++) {
                int u = tid + u0 * 256;          // 512 units: 128 rows x 4 16B-chunks
                int row = u >> 2, ch = u & 3;
                cpa16(tb + row * TSTRIDE + ch * 16, s + (size_t)row * K + ch * 8);
            }
        }
    };

    float acc[2][8][4] = {};
    const int NCK = K / BK;

    load_stage(0, 0);
    CP_COMMIT();
    if (NCK > 1) load_stage(1, 1);
    CP_COMMIT();
    if (NCK > 2) load_stage(2, 2);
    CP_COMMIT();

    int stage = 0;
    for (int kc = 0; kc < NCK; kc++) {
        CP_WAIT2();                // stage for chunk kc resident
        __syncthreads();           // all warps done with the stage we are about to refill

        int nst = stage + 3; if (nst >= NSTAGE) nst -= NSTAGE;
        if (kc + 3 < NCK) load_stage(nst, kc + 3);
        CP_COMMIT();

        const uint32_t base = sb + stage * STAGE_BYTES;
        const uint32_t A_h = base;
        const uint32_t A_l = base + TILE_BYTES;
        const uint32_t W_s = base + 2 * TILE_BYTES;

        #pragma unroll
        for (int fk = 0; fk < 2; fk++) {
            uint32_t ah[2][4], al[2][4];
            {
                int arow = wm + (lane & 15);
                int abyte = fk * 32 + ((lane >> 4) << 4);
                ldsm4(ah[0], A_h + arow * TSTRIDE + abyte);
                ldsm4(ah[1], A_h + (arow + 16) * TSTRIDE + abyte);
                ldsm4(al[0], A_l + arow * TSTRIDE + abyte);
                ldsm4(al[1], A_l + (arow + 16) * TSTRIDE + abyte);
            }
            uint32_t wv[8][2];
            {
                int brow = wn + ((lane & 16) >> 1) + (lane & 7);
                int bbyte = fk * 32 + (((lane >> 3) & 1) << 4);
                #pragma unroll
                for (int fo = 0; fo < 4; fo++) {
                    uint32_t r[4];
                    ldsm4(r, W_s + (brow + fo * 16) * TSTRIDE + bbyte);
                    wv[2 * fo][0] = r[0]; wv[2 * fo][1] = r[1];
                    wv[2 * fo + 1][0] = r[2]; wv[2 * fo + 1][1] = r[3];
                }
            }
            #pragma unroll
            for (int fm = 0; fm < 2; fm++)
                #pragma unroll
                for (int fn = 0; fn < 8; fn++) {
                    mma_f16(acc[fm][fn], ah[fm], wv[fn]);   // hi*W
                    mma_f16(acc[fm][fn], al[fm], wv[fn]);   // lo*W
                }
        }
        stage++; if (stage >= NSTAGE) stage = 0;
    }

    // ---------------- epilogue ----------------
    #pragma unroll
    for (int fm = 0; fm < 2; fm++) {
        #pragma unroll
        for (int fn = 0; fn < 8; fn++) {
            int r0 = bm + wm + fm * 16 + (lane >> 2);
            int c  = bn + wn + fn * 8 + (lane & 3) * 2;
            #pragma unroll
            for (int half_ = 0; half_ < 2; half_++) {
                size_t row = (size_t)(r0 + half_ * 8);
                float v0 = acc[fm][fn][half_ * 2];
                float v1 = acc[fm][fn][half_ * 2 + 1];
                if (bias) { v0 += bias[c]; v1 += bias[c + 1]; }
                if (res) {
                    float2 rr = *(const float2*)(res + row * N + c);
                    v0 += rr.x; v1 += rr.y;
                }
                if (relu) { v0 = fmaxf(v0, 0.f); v1 = fmaxf(v1, 0.f); }
                if (outf) *(float2*)(outf + row * N + c) = make_float2(v0, v1);
                if (outh) {
                    __half h0, l0, h1, l1;
                    f2hl(v0, h0, l0); f2hl(v1, h1, l1);
                    *(__half2*)(outh + row * N + c) = __halves2half2(h0, h1);
                    *(__half2*)(outl + row * N + c) = __halves2half2(l0, l1);
                }
            }
        }
    }
}

// ---------------- layout / prep ----------------
__global__ void prep_kernel(const float* __restrict__ data, float* __restrict__ X,
                            __half* __restrict__ Eh, __half* __restrict__ El)
{
    int idx = blockIdx.x * blockDim.x + threadIdx.x;
    if (idx >= TOTAL) return;
    int t = idx % Tt;
    int v = (idx / Tt) % Vv;
    int c = (idx / (Tt * Vv)) % Cc;
    int b = idx / (Tt * Vv * Cc);
    float val = data[idx];
    size_t o = (size_t)((b * Tt + t) * Vv + v) * Cc + c;
    X[o] = val;
    f2hl(val, Eh[o], El[o]);
}

__global__ void relay_init_kernel(const float* __restrict__ X,
                                  __half* __restrict__ Rh, __half* __restrict__ Rl)
{
    int idx = blockIdx.x * blockDim.x + threadIdx.x;
    if (idx >= Nr * Cc) return;
    int n = idx >> 8;
    int c = idx & 255;
    float s = 0.f;
    #pragma unroll
    for (int v = 0; v < Vv; v++) s += X[(size_t)(n * Vv + v) * Cc + c];
    f2hl(s * (1.0f / Vv), Rh[idx], Rl[idx]);
}

__global__ void final_kernel(const float* __restrict__ X, float* __restrict__ out)
{
    int idx = blockIdx.x * blockDim.x + threadIdx.x;
    if (idx >= TOTAL) return;
    int t = idx % Tt;
    int v = (idx / Tt) % Vv;
    int c = (idx / (Tt * Vv)) % Cc;
    int b = idx / (Tt * Vv * Cc);
    out[idx] = X[(size_t)((b * Tt + t) * Vv + v) * Cc + c];
}

// ---------------- merged weight prep (one launch per layer) ----------------
#define WPREP_TOTAL 720896
__global__ void wprep(const float* __restrict__ q, const float* __restrict__ k,
                      const float* __restrict__ v,
                      const float* __restrict__ qb, const float* __restrict__ kb,
                      const float* __restrict__ vb,
                      const float* __restrict__ f1, const float* __restrict__ f2,
                      __half* __restrict__ Wp, float* __restrict__ b,
                      __half* __restrict__ F1p, __half* __restrict__ F2p)
{
    int idx = blockIdx.x * blockDim.x + threadIdx.x;
    if (idx >= WPREP_TOTAL) return;
    if (idx < 3 * Cc)
        b[idx] = (idx < Cc) ? qb[idx] : (idx < 2 * Cc) ? kb[idx - Cc] : vb[idx - 2 * Cc];
    if (idx < 3 * Cc * Cc) {
        int row = idx >> 8;
        int col = idx & 255;
        const float* src = (row < Cc) ? q + (size_t)row * Cc
                         : (row < 2 * Cc) ? k + (size_t)(row - Cc) * Cc
                         : v + (size_t)(row - 2 * Cc) * Cc;
        Wp[idx] = __float2half_rn(src[col]);
    } else if (idx < 3 * Cc * Cc + DIN * Cc) {
        int i = idx - 3 * Cc * Cc;
        F1p[i] = __float2half_rn(f1[i]);
    } else {
        int i = idx - 3 * Cc * Cc - DIN * Cc;
        F2p[i] = __float2half_rn(f2[i]);
    }
}

// ---------------- LayerNorm ----------------
__global__ void __launch_bounds__(256) ln_kernel(const float* __restrict__ x,
                                                 const float* __restrict__ g,
                                                 const float* __restrict__ b,
                                                 float* __restrict__ y,
                                                 __half* __restrict__ yh,
                                                 __half* __restrict__ yl)
{
    int row = blockIdx.x * 8 + (threadIdx.x >> 5);
    int lane = threadIdx.x & 31;
    const float* xr = x + (size_t)row * Cc;
    float v[8];
    float s = 0.f;
    #pragma unroll
    for (int i = 0; i < 8; i++) { v[i] = xr[lane + 32 * i]; s += v[i]; }
    #pragma unroll
    for (int o = 16; o; o >>= 1) s += __shfl_xor_sync(~0u, s, o);
    float mean = s * (1.0f / Cc);
    float s2 = 0.f;
    #pragma unroll
    for (int i = 0; i < 8; i++) { float d = v[i] - mean; s2 += d * d; }
    #pragma unroll
    for (int o = 16; o; o >>= 1) s2 += __shfl_xor_sync(~0u, s2, o);
    float rs = rsqrtf(s2 * (1.0f / Cc) + 1e-6f);
    #pragma unroll
    for (int i = 0; i < 8; i++) {
        int c = lane + 32 * i;
        size_t o = (size_t)row * Cc + c;
        float yv = (v[i] - mean) * rs * g[c] + b[c];
        y[o] = yv;
        f2hl(yv, yh[o], yl[o]);
    }
}

// ---------------- graph attention (7 slots), packed inputs ----------------
__global__ void __launch_bounds__(256) attn_j(const float* __restrict__ QKV,
                                              const float* __restrict__ AKV,
                                              const float* __restrict__ AKVr,
                                              const float* __restrict__ xn,
                                              float* __restrict__ y1)
{
    int p = blockIdx.x;
    int co = threadIdx.x;
    int n = p / Vv, l = p - n * Vv;
    size_t qbase = (size_t)p * 768 + co;
    size_t abase = (size_t)p * 512 + co;
    size_t rbase = (size_t)n * 512 + co;
    float q = QKV[qbase];
    int deg = c_deg[l];
    float sc[7];
    #pragma unroll
    for (int w = 0; w < 5; w++) {
        float d = -1e30f;
        if (w < deg) {
            int j = c_nbr[l][w];
            float dd = q * QKV[(size_t)(n * Vv + j) * 768 + 256 + co];
            #pragma unroll
            for (int o = 16; o; o >>= 1) dd += __shfl_xor_sync(~0u, dd, o);
            d = dd * INV_SQRT_DK;
        }
        sc[w] = d;
    }
    {
        float dd = q * AKV[abase];
        #pragma unroll
        for (int o = 16; o; o >>= 1) dd += __shfl_xor_sync(~0u, dd, o);
        sc[5] = dd * INV_SQRT_DK;
        dd = q * AKVr[rbase];
        #pragma unroll
        for (int o = 16; o; o >>= 1) dd += __shfl_xor_sync(~0u, dd, o);
        sc[6] = dd * INV_SQRT_DK;
    }
    float mx = sc[0];
    #pragma unroll
    for (int w = 1; w < 7; w++) mx = fmaxf(mx, sc[w]);
    float wg[7];
    float sum = 0.f;
    #pragma unroll
    for (int w = 0; w < 7; w++) { wg[w] = expf(sc[w] - mx); sum += wg[w]; }
    float att = 0.f;
    #pragma unroll
    for (int w = 0; w < 5; w++)
        if (w < deg) att += wg[w] * QKV[(size_t)(n * Vv + c_nbr[l][w]) * 768 + 512 + co];
    att += wg[5] * AKV[abase + 256] + wg[6] * AKVr[rbase + 256];
    y1[(size_t)p * Cc + co] = xn[(size_t)p * Cc + co] + att / sum;
}

// ---------------- BatchNorm (axes 0,2) ----------------
__global__ void bn_zero(float* __restrict__ stats)
{
    int i = blockIdx.x * blockDim.x + threadIdx.x;
    if (i < 2 * Cc) stats[i] = 0.f;
}

__global__ void __launch_bounds__(256) bn_stats(const float* __restrict__ x,
                                                float* __restrict__ stats, int rows)
{
    int c = threadIdx.x;
    int r0 = blockIdx.x * 64;
    float s = 0.f, s2 = 0.f;
    for (int r = r0; r < r0 + 64; r++) {
        float v = x[(size_t)r * Cc + c];
        s += v; s2 += v * v;
    }
    atomicAdd(&stats[c], s);
    atomicAdd(&stats[Cc + c], s2);
}

__global__ void __launch_bounds__(256) bn_apply(const float* __restrict__ x,
                                                const float* __restrict__ stats,
                                                const float* __restrict__ g,
                                                const float* __restrict__ b,
                                                float* __restrict__ y,
                                                __half* __restrict__ yh,
                                                __half* __restrict__ yl,
                                                int rows, int leaky)
{
    int idx = blockIdx.x * blockDim.x + threadIdx.x;
    if (idx >= rows * Cc) return;
    int c = idx & 255;
    float inv = 1.0f / rows;
    float mean = stats[c] * inv;
    float var = stats[Cc + c] * inv - mean * mean;
    float v = (x[idx] - mean) * rsqrtf(var + 1e-5f) * g[c] + b[c];
    if (leaky) v = v > 0.f ? v : 0.01f * v;
    y[idx] = v;
    if (yh) f2hl(v, yh[idx], yl[idx]);
}

// ---------------- host ----------------
template <typename Sym>
static float* sym_f(const Sym& s) { void* p = nullptr; cudaGetSymbolAddress(&p, s); return (float*)p; }
template <typename Sym>
static __half* sym_h(const Sym& s) { void* p = nullptr; cudaGetSymbolAddress(&p, s); return (__half*)p; }

extern "C" void kernel_launch(void* const* d_in, const int* in_sizes, int n_in,
                              void* d_out, int out_size)
{
    const float* data  = (const float*)d_in[0];
    const float* ln_g  = (const float*)d_in[1];
    const float* ln_b  = (const float*)d_in[2];
    const float* jq_w  = (const float*)d_in[3];
    const float* jq_b  = (const float*)d_in[4];
    const float* jk_w  = (const float*)d_in[5];
    const float* jk_b  = (const float*)d_in[6];
    const float* jv_w  = (const float*)d_in[7];
    const float* jv_b  = (const float*)d_in[8];
    const float* jbn_g = (const float*)d_in[9];
    const float* jbn_b = (const float*)d_in[10];
    const float* jf1_w = (const float*)d_in[11];
    const float* jf1_b = (const float*)d_in[12];
    const float* jf2_w = (const float*)d_in[13];
    const float* jf2_b = (const float*)d_in[14];
    const float* jfbn_g = (const float*)d_in[15];
    const float* jfbn_b = (const float*)d_in[16];
    // relay-path weights (d_in[17..30]) are dead: relay never feeds back into nodes.

    float* X    = sym_f(g_X);
    float* xn   = sym_f(g_xn);
    float* QKV  = sym_f(g_QKV);
    float* AKV  = sym_f(g_AKV);
    float* AKVr = sym_f(g_AKVr);
    float* y1   = sym_f(g_y1);
    float* ret  = sym_f(g_ret);
    float* F    = sym_f(g_F);
    float* bj   = sym_f(g_bj);
    float* stats = sym_f(g_stats);
    __half *Eh = sym_h(g_Eh), *El = sym_h(g_El);
    __half *Rh = sym_h(g_Rh), *Rl = sym_h(g_Rl);
    __half *xnh = sym_h(g_xnh), *xnl = sym_h(g_xnl);
    __half *reth = sym_h(g_reth), *retl = sym_h(g_retl);
    __half *Hh = sym_h(g_Hh), *Hl = sym_h(g_Hl);
    __half *Wj = sym_h(g_Wj);
    __half *F1 = sym_h(g_F1);
    __half *F2 = sym_h(g_F2);

    static bool attr_set = false;
    if (!attr_set) {
        cudaFuncSetAttribute(gemm_mma, cudaFuncAttributeMaxDynamicSharedMemorySize, GEMM_SMEM);
        attr_set = true;
    }

    prep_kernel<<<(TOTAL + 255) / 256, 256>>>(data, X, Eh, El);
    relay_init_kernel<<<(Nr * Cc + 255) / 256, 256>>>(X, Rh, Rl);

    for (int ly = 0; ly < 2; ly++) {
        wprep<<<(WPREP_TOTAL + 255) / 256, 256>>>(
            jq_w + (size_t)ly * Cc * Cc, jk_w + (size_t)ly * Cc * Cc,
            jv_w + (size_t)ly * Cc * Cc,
            jq_b + ly * Cc, jk_b + ly * Cc, jv_b + ly * Cc,
            jf1_w + (size_t)ly * DIN * Cc, jf2_w + (size_t)ly * Cc * DIN,
            Wj + (size_t)ly * 3 * Cc * Cc, bj + (size_t)ly * 3 * Cc,
            F1 + (size_t)ly * DIN * Cc, F2 + (size_t)ly * Cc * DIN);
    }

    for (int ly = 0; ly < 2; ly++) {
        const float* lg  = ln_g + ly * Cc;
        const float* lb  = ln_b + ly * Cc;
        const __half* Wl = Wj + (size_t)ly * 3 * Cc * Cc;
        const float* bl  = bj + (size_t)ly * 3 * Cc;
        const float* bng = jbn_g + ly * Cc;
        const float* bnb = jbn_b + ly * Cc;
        const __half* f1p = F1 + (size_t)ly * DIN * Cc;
        const float* f1b = jf1_b + ly * DIN;
        const __half* f2p = F2 + (size_t)ly * Cc * DIN;
        const float* f2b = jf2_b + ly * Cc;
        const float* fbg = jfbn_g + ly * Cc;
        const float* fbb = jfbn_b + ly * Cc;

        ln_kernel<<<Pp / 8, 256>>>(X, lg, lb, xn, xnh, xnl);

        // QKV: [Pp,768] = xn @ Wqkv^T
        gemm_mma<<<dim3(768 / 128, Pp / 128), 256, GEMM_SMEM>>>(
            xnh, xnl, Wl, bl, nullptr, QKV, nullptr, nullptr, Pp, 768, Cc, 0);
        // AKe|AVe: [Pp,512] = embs @ Wkv^T
        gemm_mma<<<dim3(512 / 128, Pp / 128), 256, GEMM_SMEM>>>(
            Eh, El, Wl + (size_t)Cc * Cc, bl + Cc, nullptr,
            AKV, nullptr, nullptr, Pp, 512, Cc, 0);
        // AKr|AVr: [Nr,512] = relay0 @ Wkv^T
        gemm_mma<<<dim3(512 / 128, Nr / 128), 256, GEMM_SMEM>>>(
            Rh, Rl, Wl + (size_t)Cc * Cc, bl + Cc, nullptr,
            AKVr, nullptr, nullptr, Nr, 512, Cc, 0);

        attn_j<<<Pp, 256>>>(QKV, AKV, AKVr, xn, y1);

        bn_zero<<<2, 256>>>(stats);
        bn_stats<<<Pp / 64, 256>>>(y1, stats, Pp);
        bn_apply<<<(Pp * Cc + 255) / 256, 256>>>(y1, stats, bng, bnb, ret, reth, retl, Pp, 0);

        // FFN1: H = relu(ret @ f1^T + b1), written directly as hi/lo fp16
        gemm_mma<<<dim3(DIN / 128, Pp / 128), 256, GEMM_SMEM>>>(
            reth, retl, f1p, f1b, nullptr, nullptr, Hh, Hl, Pp, DIN, Cc, 1);
        // FFN2: F = H @ f2^T + b2 + ret
        gemm_mma<<<dim3(Cc / 128, Pp / 128), 256, GEMM_SMEM>>>(
            Hh, Hl, f2p, f2b, ret, F, nullptr, nullptr, Pp, Cc, DIN, 0);

        bn_zero<<<2, 256>>>(stats);
        bn_stats<<<Pp / 64, 256>>>(F, stats, Pp);
        bn_apply<<<(Pp * Cc + 255) / 256, 256>>>(F, stats, fbg, fbb, X, nullptr, nullptr, Pp, 1);
    }

    final_kernel<<<(TOTAL + 255) / 256, 256>>>(X, (float*)d_out);
}

// round 12
// speedup vs baseline: 3.9514x; 1.1339x over previous
#include <cuda_runtime.h>
#include <cuda_fp16.h>
#include <math.h>
#include <stdint.h>

// Problem constants
#define Cc 256
#define Vv 17
#define Tt 256
#define Nr 1024            // B*T
#define Pp 17408           // Nr*Vv
#define DIN 1024
#define TOTAL 4456448      // B*C*V*T
#define INV_SQRT_DK 0.17677669529663687f

// 0-indexed adjacency (padded), degrees
__constant__ int c_nbr[17][5] = {
    {0,1,2,5,6},{0,1,3,0,0},{0,2,4,0,0},{1,3,0,0,0},{2,4,0,0,0},
    {0,5,7,11,0},{0,6,8,12,0},{5,7,9,0,0},{6,8,12,0,0},{7,9,0,0,0},
    {8,10,0,0,0},{8,11,13,0,0},{10,12,14,0,0},{11,13,15,0,0},{12,14,16,0,0},
    {13,15,0,0,0},{14,16,0,0,0}
};
__constant__ int c_deg[17] = {5,3,3,2,2,4,4,3,3,2,2,3,3,3,3,2,2};

// fp32 scratch
__device__ float g_X[Pp*Cc];
__device__ float g_xn[Pp*Cc];
__device__ float g_QKV[Pp*3*Cc];
__device__ float g_AKV[Pp*2*Cc];
__device__ float g_AKVr[Nr*2*Cc];
__device__ float g_y1[Pp*Cc];
__device__ float g_ret[Pp*Cc];
__device__ float g_F[Pp*Cc];
__device__ float g_bj[2*3*Cc];
__device__ float g_stats[2*Cc];
// fp16 hi/lo activation scratch (A operands) + fp16 weights (W operands)
__device__ __half g_Eh[Pp*Cc],  g_El[Pp*Cc];
__device__ __half g_Rh[Nr*Cc],  g_Rl[Nr*Cc];
__device__ __half g_xnh[Pp*Cc], g_xnl[Pp*Cc];
__device__ __half g_reth[Pp*Cc], g_retl[Pp*Cc];
__device__ __half g_Hh[Pp*DIN], g_Hl[Pp*DIN];
__device__ __half g_Wj[2*3*Cc*Cc];
__device__ __half g_F1[2*DIN*Cc];
__device__ __half g_F2[2*Cc*DIN];

// ---------------- helpers ----------------
__device__ __forceinline__ uint32_t smem_u32(const void* p) {
    return (uint32_t)__cvta_generic_to_shared(p);
}
__device__ __forceinline__ void cpa16(uint32_t d, const void* s) {
    asm volatile("cp.async.cg.shared.global [%0], [%1], 16;" :: "r"(d), "l"(s));
}
#define CP_COMMIT() asm volatile("cp.async.commit_group;" ::: "memory")
#define CP_WAIT1()  asm volatile("cp.async.wait_group 1;" ::: "memory")
__device__ __forceinline__ void ldsm4(uint32_t* r, uint32_t a) {
    asm volatile("ldmatrix.sync.aligned.m8n8.x4.shared.b16 {%0,%1,%2,%3}, [%4];"
                 : "=r"(r[0]), "=r"(r[1]), "=r"(r[2]), "=r"(r[3]) : "r"(a));
}
__device__ __forceinline__ void mma_f16(float* c, const uint32_t* a, const uint32_t* b) {
    asm volatile("mma.sync.aligned.m16n8k16.row.col.f32.f16.f16.f32 "
                 "{%0,%1,%2,%3}, {%4,%5,%6,%7}, {%8,%9}, {%0,%1,%2,%3};"
                 : "+f"(c[0]), "+f"(c[1]), "+f"(c[2]), "+f"(c[3])
                 : "r"(a[0]), "r"(a[1]), "r"(a[2]), "r"(a[3]), "r"(b[0]), "r"(b[1]));
}
__device__ __forceinline__ void f2hl(float v, __half& h, __half& l) {
    h = __float2half_rn(v);
    l = __float2half_rn(v - __half2float(h));
}

// ---------------- tensor-core GEMM (mma.sync fp16x2), 3-stage, 2 CTAs/SM ----------------
// out = A @ W^T; A[M,K] split hi/lo fp16, W[N,K] fp16, K-major.
// M%128==0, N%128==0, K%32==0.
#define BK 32
#define TSTRIDE 80                      // padded bytes per smem row (conflict-free ldmatrix)
#define TILE_BYTES (128*TSTRIDE)        // 10240
#define STAGE_BYTES (3*TILE_BYTES)      // 30720
#define NSTAGE 3
#define GEMM_SMEM (NSTAGE*STAGE_BYTES)  // 92160 -> 2 CTAs/SM

__global__ void __launch_bounds__(256) gemm_mma(
    const __half* __restrict__ Ah, const __half* __restrict__ Al,
    const __half* __restrict__ W,
    const float* __restrict__ bias, const float* __restrict__ res,
    float* __restrict__ outf,
    __half* __restrict__ outh, __half* __restrict__ outl,
    int M, int N, int K, int relu, float* __restrict__ zstats)
{
    extern __shared__ char smem[];
    const uint32_t sb = smem_u32(smem);
    const int tid = threadIdx.x;
    const int warp = tid >> 5, lane = tid & 31;
    const int bm = blockIdx.y * 128;
    const int bn = blockIdx.x * 128;
    const int wm = (warp >> 1) * 32;
    const int wn = (warp & 1) * 64;

    // fold bn_zero into the producer GEMM (block (0,0) zeroes the stats buffer)
    if (zstats && bm == 0 && bn == 0 && tid < 256) {
        zstats[tid] = 0.f;
        zstats[256 + tid] = 0.f;
    }

    const __half* srcs[3] = {
        Ah + (size_t)bm * K, Al + (size_t)bm * K, W + (size_t)bn * K
    };

    auto load_stage = [&](int stage, int kc) {
        const uint32_t base = sb + stage * STAGE_BYTES;
        const int k0 = kc * BK;
        #pragma unroll
        for (int t2 = 0; t2 < 3; t2++) {
            const uint32_t tb = base + t2 * TILE_BYTES;
            const __half* s = srcs[t2] + k0;
            #pragma unroll
            for (int u0 = 0; u0 < 2; u0++) {
                int u = tid + u0 * 256;          // 512 units: 128 rows x 4 16B-chunks
                int row = u >> 2, ch = u & 3;
                cpa16(tb + row * TSTRIDE + ch * 16, s + (size_t)row * K + ch * 8);
            }
        }
    };

    float acc[2][8][4] = {};
    const int NCK = K / BK;

    load_stage(0, 0);
    CP_COMMIT();
    if (NCK > 1) load_stage(1, 1);
    CP_COMMIT();

    int stage = 0;
    for (int kc = 0; kc < NCK; kc++) {
        CP_WAIT1();                // stage for chunk kc resident
        __syncthreads();           // all warps done with the stage we are about to refill

        int nst = stage + 2; if (nst >= NSTAGE) nst -= NSTAGE;
        if (kc + 2 < NCK) load_stage(nst, kc + 2);
        CP_COMMIT();

        const uint32_t base = sb + stage * STAGE_BYTES;
        const uint32_t A_h = base;
        const uint32_t A_l = base + TILE_BYTES;
        const uint32_t W_s = base + 2 * TILE_BYTES;

        #pragma unroll
        for (int fk = 0; fk < 2; fk++) {
            uint32_t ah[2][4], al[2][4];
            {
                int arow = wm + (lane & 15);
                int abyte = fk * 32 + ((lane >> 4) << 4);
                ldsm4(ah[0], A_h + arow * TSTRIDE + abyte);
                ldsm4(ah[1], A_h + (arow + 16) * TSTRIDE + abyte);
                ldsm4(al[0], A_l + arow * TSTRIDE + abyte);
                ldsm4(al[1], A_l + (arow + 16) * TSTRIDE + abyte);
            }
            uint32_t wv[8][2];
            {
                int brow = wn + ((lane & 16) >> 1) + (lane & 7);
                int bbyte = fk * 32 + (((lane >> 3) & 1) << 4);
                #pragma unroll
                for (int fo = 0; fo < 4; fo++) {
                    uint32_t r[4];
                    ldsm4(r, W_s + (brow + fo * 16) * TSTRIDE + bbyte);
                    wv[2 * fo][0] = r[0]; wv[2 * fo][1] = r[1];
                    wv[2 * fo + 1][0] = r[2]; wv[2 * fo + 1][1] = r[3];
                }
            }
            #pragma unroll
            for (int fm = 0; fm < 2; fm++)
                #pragma unroll
                for (int fn = 0; fn < 8; fn++) {
                    mma_f16(acc[fm][fn], ah[fm], wv[fn]);   // hi*W
                    mma_f16(acc[fm][fn], al[fm], wv[fn]);   // lo*W
                }
        }
        stage++; if (stage >= NSTAGE) stage = 0;
    }

    // ---------------- epilogue ----------------
    #pragma unroll
    for (int fm = 0; fm < 2; fm++) {
        #pragma unroll
        for (int fn = 0; fn < 8; fn++) {
            int r0 = bm + wm + fm * 16 + (lane >> 2);
            int c  = bn + wn + fn * 8 + (lane & 3) * 2;
            #pragma unroll
            for (int half_ = 0; half_ < 2; half_++) {
                size_t row = (size_t)(r0 + half_ * 8);
                float v0 = acc[fm][fn][half_ * 2];
                float v1 = acc[fm][fn][half_ * 2 + 1];
                if (bias) { v0 += bias[c]; v1 += bias[c + 1]; }
                if (res) {
                    float2 rr = *(const float2*)(res + row * N + c);
                    v0 += rr.x; v1 += rr.y;
                }
                if (relu) { v0 = fmaxf(v0, 0.f); v1 = fmaxf(v1, 0.f); }
                if (outf) *(float2*)(outf + row * N + c) = make_float2(v0, v1);
                if (outh) {
                    __half h0, l0, h1, l1;
                    f2hl(v0, h0, l0); f2hl(v1, h1, l1);
                    *(__half2*)(outh + row * N + c) = __halves2half2(h0, h1);
                    *(__half2*)(outl + row * N + c) = __halves2half2(l0, l1);
                }
            }
        }
    }
}

// ---------------- layout / prep ----------------
__global__ void prep_kernel(const float* __restrict__ data, float* __restrict__ X,
                            __half* __restrict__ Eh, __half* __restrict__ El)
{
    int idx = blockIdx.x * blockDim.x + threadIdx.x;
    if (idx >= TOTAL) return;
    int t = idx % Tt;
    int v = (idx / Tt) % Vv;
    int c = (idx / (Tt * Vv)) % Cc;
    int b = idx / (Tt * Vv * Cc);
    float val = data[idx];
    size_t o = (size_t)((b * Tt + t) * Vv + v) * Cc + c;
    X[o] = val;
    f2hl(val, Eh[o], El[o]);
}

__global__ void relay_init_kernel(const float* __restrict__ X,
                                  __half* __restrict__ Rh, __half* __restrict__ Rl)
{
    int idx = blockIdx.x * blockDim.x + threadIdx.x;
    if (idx >= Nr * Cc) return;
    int n = idx >> 8;
    int c = idx & 255;
    float s = 0.f;
    #pragma unroll
    for (int v = 0; v < Vv; v++) s += X[(size_t)(n * Vv + v) * Cc + c];
    f2hl(s * (1.0f / Vv), Rh[idx], Rl[idx]);
}

// ---------------- merged weight prep (one launch per layer) ----------------
#define WPREP_TOTAL 720896
__global__ void wprep(const float* __restrict__ q, const float* __restrict__ k,
                      const float* __restrict__ v,
                      const float* __restrict__ qb, const float* __restrict__ kb,
                      const float* __restrict__ vb,
                      const float* __restrict__ f1, const float* __restrict__ f2,
                      __half* __restrict__ Wp, float* __restrict__ b,
                      __half* __restrict__ F1p, __half* __restrict__ F2p)
{
    int idx = blockIdx.x * blockDim.x + threadIdx.x;
    if (idx >= WPREP_TOTAL) return;
    if (idx < 3 * Cc)
        b[idx] = (idx < Cc) ? qb[idx] : (idx < 2 * Cc) ? kb[idx - Cc] : vb[idx - 2 * Cc];
    if (idx < 3 * Cc * Cc) {
        int row = idx >> 8;
        int col = idx & 255;
        const float* src = (row < Cc) ? q + (size_t)row * Cc
                         : (row < 2 * Cc) ? k + (size_t)(row - Cc) * Cc
                         : v + (size_t)(row - 2 * Cc) * Cc;
        Wp[idx] = __float2half_rn(src[col]);
    } else if (idx < 3 * Cc * Cc + DIN * Cc) {
        int i = idx - 3 * Cc * Cc;
        F1p[i] = __float2half_rn(f1[i]);
    } else {
        int i = idx - 3 * Cc * Cc - DIN * Cc;
        F2p[i] = __float2half_rn(f2[i]);
    }
}

// ---------------- LayerNorm (layer-0 entry: reads X) ----------------
__global__ void __launch_bounds__(256) ln_kernel(const float* __restrict__ x,
                                                 const float* __restrict__ g,
                                                 const float* __restrict__ b,
                                                 float* __restrict__ y,
                                                 __half* __restrict__ yh,
                                                 __half* __restrict__ yl)
{
    int row = blockIdx.x * 8 + (threadIdx.x >> 5);
    int lane = threadIdx.x & 31;
    const float* xr = x + (size_t)row * Cc;
    float v[8];
    float s = 0.f;
    #pragma unroll
    for (int i = 0; i < 8; i++) { v[i] = xr[lane + 32 * i]; s += v[i]; }
    #pragma unroll
    for (int o = 16; o; o >>= 1) s += __shfl_xor_sync(~0u, s, o);
    float mean = s * (1.0f / Cc);
    float s2 = 0.f;
    #pragma unroll
    for (int i = 0; i < 8; i++) { float d = v[i] - mean; s2 += d * d; }
    #pragma unroll
    for (int o = 16; o; o >>= 1) s2 += __shfl_xor_sync(~0u, s2, o);
    float rs = rsqrtf(s2 * (1.0f / Cc) + 1e-6f);
    #pragma unroll
    for (int i = 0; i < 8; i++) {
        int c = lane + 32 * i;
        size_t o = (size_t)row * Cc + c;
        float yv = (v[i] - mean) * rs * g[c] + b[c];
        y[o] = yv;
        f2hl(yv, yh[o], yl[o]);
    }
}

// ---------------- fused BN(leaky) + LN  (layer boundary; skips X round-trip) --------
__global__ void __launch_bounds__(256) bnln_kernel(const float* __restrict__ F,
                                                   const float* __restrict__ stats,
                                                   const float* __restrict__ fg,
                                                   const float* __restrict__ fb,
                                                   const float* __restrict__ lg,
                                                   const float* __restrict__ lb,
                                                   float* __restrict__ y,
                                                   __half* __restrict__ yh,
                                                   __half* __restrict__ yl)
{
    int row = blockIdx.x * 8 + (threadIdx.x >> 5);
    int lane = threadIdx.x & 31;
    const float* xr = F + (size_t)row * Cc;
    const float inv = 1.0f / Pp;
    float v[8];
    float s = 0.f;
    #pragma unroll
    for (int i = 0; i < 8; i++) {
        int c = lane + 32 * i;
        float mean = stats[c] * inv;
        float var = stats[Cc + c] * inv - mean * mean;
        float t = (xr[c] - mean) * rsqrtf(var + 1e-5f) * fg[c] + fb[c];
        t = t > 0.f ? t : 0.01f * t;          // leaky
        v[i] = t;
        s += t;
    }
    #pragma unroll
    for (int o = 16; o; o >>= 1) s += __shfl_xor_sync(~0u, s, o);
    float mean = s * (1.0f / Cc);
    float s2 = 0.f;
    #pragma unroll
    for (int i = 0; i < 8; i++) { float d = v[i] - mean; s2 += d * d; }
    #pragma unroll
    for (int o = 16; o; o >>= 1) s2 += __shfl_xor_sync(~0u, s2, o);
    float rs = rsqrtf(s2 * (1.0f / Cc) + 1e-6f);
    #pragma unroll
    for (int i = 0; i < 8; i++) {
        int c = lane + 32 * i;
        size_t o = (size_t)row * Cc + c;
        float yv = (v[i] - mean) * rs * lg[c] + lb[c];
        y[o] = yv;
        f2hl(yv, yh[o], yl[o]);
    }
}

// ---------------- fused BN(leaky) + output transpose (final layer) ----------------
__global__ void __launch_bounds__(256) bnfinal_kernel(const float* __restrict__ F,
                                                      const float* __restrict__ stats,
                                                      const float* __restrict__ g,
                                                      const float* __restrict__ b,
                                                      float* __restrict__ out)
{
    int idx = blockIdx.x * blockDim.x + threadIdx.x;
    if (idx >= TOTAL) return;
    int t = idx % Tt;
    int v = (idx / Tt) % Vv;
    int c = (idx / (Tt * Vv)) % Cc;
    int bb = idx / (Tt * Vv * Cc);
    float f = F[(size_t)((bb * Tt + t) * Vv + v) * Cc + c];
    const float inv = 1.0f / Pp;
    float mean = stats[c] * inv;
    float var = stats[Cc + c] * inv - mean * mean;
    float val = (f - mean) * rsqrtf(var + 1e-5f) * g[c] + b[c];
    out[idx] = val > 0.f ? val : 0.01f * val;
}

// ---------------- graph attention (7 slots), packed inputs ----------------
__global__ void __launch_bounds__(256) attn_j(const float* __restrict__ QKV,
                                              const float* __restrict__ AKV,
                                              const float* __restrict__ AKVr,
                                              const float* __restrict__ xn,
                                              float* __restrict__ y1,
                                              float* __restrict__ zstats)
{
    int p = blockIdx.x;
    int co = threadIdx.x;
    if (p == 0) { zstats[co] = 0.f; zstats[256 + co] = 0.f; }   // fold bn_zero
    int n = p / Vv, l = p - n * Vv;
    size_t qbase = (size_t)p * 768 + co;
    size_t abase = (size_t)p * 512 + co;
    size_t rbase = (size_t)n * 512 + co;
    float q = QKV[qbase];
    int deg = c_deg[l];
    float sc[7];
    #pragma unroll
    for (int w = 0; w < 5; w++) {
        float d = -1e30f;
        if (w < deg) {
            int j = c_nbr[l][w];
            float dd = q * QKV[(size_t)(n * Vv + j) * 768 + 256 + co];
            #pragma unroll
            for (int o = 16; o; o >>= 1) dd += __shfl_xor_sync(~0u, dd, o);
            d = dd * INV_SQRT_DK;
        }
        sc[w] = d;
    }
    {
        float dd = q * AKV[abase];
        #pragma unroll
        for (int o = 16; o; o >>= 1) dd += __shfl_xor_sync(~0u, dd, o);
        sc[5] = dd * INV_SQRT_DK;
        dd = q * AKVr[rbase];
        #pragma unroll
        for (int o = 16; o; o >>= 1) dd += __shfl_xor_sync(~0u, dd, o);
        sc[6] = dd * INV_SQRT_DK;
    }
    float mx = sc[0];
    #pragma unroll
    for (int w = 1; w < 7; w++) mx = fmaxf(mx, sc[w]);
    float wg[7];
    float sum = 0.f;
    #pragma unroll
    for (int w = 0; w < 7; w++) { wg[w] = expf(sc[w] - mx); sum += wg[w]; }
    float att = 0.f;
    #pragma unroll
    for (int w = 0; w < 5; w++)
        if (w < deg) att += wg[w] * QKV[(size_t)(n * Vv + c_nbr[l][w]) * 768 + 512 + co];
    att += wg[5] * AKV[abase + 256] + wg[6] * AKVr[rbase + 256];
    y1[(size_t)p * Cc + co] = xn[(size_t)p * Cc + co] + att / sum;
}

// ---------------- BatchNorm (axes 0,2) ----------------
__global__ void __launch_bounds__(256) bn_stats(const float* __restrict__ x,
                                                float* __restrict__ stats, int rows)
{
    int c = threadIdx.x;
    int r0 = blockIdx.x * 64;
    float s = 0.f, s2 = 0.f;
    for (int r = r0; r < r0 + 64; r++) {
        float v = x[(size_t)r * Cc + c];
        s += v; s2 += v * v;
    }
    atomicAdd(&stats[c], s);
    atomicAdd(&stats[Cc + c], s2);
}

__global__ void __launch_bounds__(256) bn_apply(const float* __restrict__ x,
                                                const float* __restrict__ stats,
                                                const float* __restrict__ g,
                                                const float* __restrict__ b,
                                                float* __restrict__ y,
                                                __half* __restrict__ yh,
                                                __half* __restrict__ yl,
                                                int rows, int leaky)
{
    int idx = blockIdx.x * blockDim.x + threadIdx.x;
    if (idx >= rows * Cc) return;
    int c = idx & 255;
    float inv = 1.0f / rows;
    float mean = stats[c] * inv;
    float var = stats[Cc + c] * inv - mean * mean;
    float v = (x[idx] - mean) * rsqrtf(var + 1e-5f) * g[c] + b[c];
    if (leaky) v = v > 0.f ? v : 0.01f * v;
    y[idx] = v;
    if (yh) f2hl(v, yh[idx], yl[idx]);
}

// ---------------- host ----------------
template <typename Sym>
static float* sym_f(const Sym& s) { void* p = nullptr; cudaGetSymbolAddress(&p, s); return (float*)p; }
template <typename Sym>
static __half* sym_h(const Sym& s) { void* p = nullptr; cudaGetSymbolAddress(&p, s); return (__half*)p; }

extern "C" void kernel_launch(void* const* d_in, const int* in_sizes, int n_in,
                              void* d_out, int out_size)
{
    const float* data  = (const float*)d_in[0];
    const float* ln_g  = (const float*)d_in[1];
    const float* ln_b  = (const float*)d_in[2];
    const float* jq_w  = (const float*)d_in[3];
    const float* jq_b  = (const float*)d_in[4];
    const float* jk_w  = (const float*)d_in[5];
    const float* jk_b  = (const float*)d_in[6];
    const float* jv_w  = (const float*)d_in[7];
    const float* jv_b  = (const float*)d_in[8];
    const float* jbn_g = (const float*)d_in[9];
    const float* jbn_b = (const float*)d_in[10];
    const float* jf1_w = (const float*)d_in[11];
    const float* jf1_b = (const float*)d_in[12];
    const float* jf2_w = (const float*)d_in[13];
    const float* jf2_b = (const float*)d_in[14];
    const float* jfbn_g = (const float*)d_in[15];
    const float* jfbn_b = (const float*)d_in[16];
    // relay-path weights (d_in[17..30]) are dead: relay never feeds back into nodes.

    float* X    = sym_f(g_X);
    float* xn   = sym_f(g_xn);
    float* QKV  = sym_f(g_QKV);
    float* AKV  = sym_f(g_AKV);
    float* AKVr = sym_f(g_AKVr);
    float* y1   = sym_f(g_y1);
    float* ret  = sym_f(g_ret);
    float* F    = sym_f(g_F);
    float* bj   = sym_f(g_bj);
    float* stats = sym_f(g_stats);
    __half *Eh = sym_h(g_Eh), *El = sym_h(g_El);
    __half *Rh = sym_h(g_Rh), *Rl = sym_h(g_Rl);
    __half *xnh = sym_h(g_xnh), *xnl = sym_h(g_xnl);
    __half *reth = sym_h(g_reth), *retl = sym_h(g_retl);
    __half *Hh = sym_h(g_Hh), *Hl = sym_h(g_Hl);
    __half *Wj = sym_h(g_Wj);
    __half *F1 = sym_h(g_F1);
    __half *F2 = sym_h(g_F2);

    static bool attr_set = false;
    if (!attr_set) {
        cudaFuncSetAttribute(gemm_mma, cudaFuncAttributeMaxDynamicSharedMemorySize, GEMM_SMEM);
        attr_set = true;
    }

    prep_kernel<<<(TOTAL + 255) / 256, 256>>>(data, X, Eh, El);
    relay_init_kernel<<<(Nr * Cc + 255) / 256, 256>>>(X, Rh, Rl);

    for (int ly = 0; ly < 2; ly++) {
        wprep<<<(WPREP_TOTAL + 255) / 256, 256>>>(
            jq_w + (size_t)ly * Cc * Cc, jk_w + (size_t)ly * Cc * Cc,
            jv_w + (size_t)ly * Cc * Cc,
            jq_b + ly * Cc, jk_b + ly * Cc, jv_b + ly * Cc,
            jf1_w + (size_t)ly * DIN * Cc, jf2_w + (size_t)ly * Cc * DIN,
            Wj + (size_t)ly * 3 * Cc * Cc, bj + (size_t)ly * 3 * Cc,
            F1 + (size_t)ly * DIN * Cc, F2 + (size_t)ly * Cc * DIN);
    }

    // layer-0 entry LN reads X
    ln_kernel<<<Pp / 8, 256>>>(X, ln_g, ln_b, xn, xnh, xnl);

    for (int ly = 0; ly < 2; ly++) {
        const __half* Wl = Wj + (size_t)ly * 3 * Cc * Cc;
        const float* bl  = bj + (size_t)ly * 3 * Cc;
        const float* bng = jbn_g + ly * Cc;
        const float* bnb = jbn_b + ly * Cc;
        const __half* f1p = F1 + (size_t)ly * DIN * Cc;
        const float* f1b = jf1_b + ly * DIN;
        const __half* f2p = F2 + (size_t)ly * Cc * DIN;
        const float* f2b = jf2_b + ly * Cc;
        const float* fbg = jfbn_g + ly * Cc;
        const float* fbb = jfbn_b + ly * Cc;

        // QKV: [Pp,768] = xn @ Wqkv^T
        gemm_mma<<<dim3(768 / 128, Pp / 128), 256, GEMM_SMEM>>>(
            xnh, xnl, Wl, bl, nullptr, QKV, nullptr, nullptr, Pp, 768, Cc, 0, nullptr);
        // AKe|AVe: [Pp,512] = embs @ Wkv^T
        gemm_mma<<<dim3(512 / 128, Pp / 128), 256, GEMM_SMEM>>>(
            Eh, El, Wl + (size_t)Cc * Cc, bl + Cc, nullptr,
            AKV, nullptr, nullptr, Pp, 512, Cc, 0, nullptr);
        // AKr|AVr: [Nr,512] = relay0 @ Wkv^T
        gemm_mma<<<dim3(512 / 128, Nr / 128), 256, GEMM_SMEM>>>(
            Rh, Rl, Wl + (size_t)Cc * Cc, bl + Cc, nullptr,
            AKVr, nullptr, nullptr, Nr, 512, Cc, 0, nullptr);

        attn_j<<<Pp, 256>>>(QKV, AKV, AKVr, xn, y1, stats);

        bn_stats<<<Pp / 64, 256>>>(y1, stats, Pp);
        bn_apply<<<(Pp * Cc + 255) / 256, 256>>>(y1, stats, bng, bnb, ret, reth, retl, Pp, 0);

        // FFN1: H = relu(ret @ f1^T + b1), written directly as hi/lo fp16
        gemm_mma<<<dim3(DIN / 128, Pp / 128), 256, GEMM_SMEM>>>(
            reth, retl, f1p, f1b, nullptr, nullptr, Hh, Hl, Pp, DIN, Cc, 1, nullptr);
        // FFN2: F = H @ f2^T + b2 + ret  (also zeroes stats for the next bn_stats)
        gemm_mma<<<dim3(Cc / 128, Pp / 128), 256, GEMM_SMEM>>>(
            Hh, Hl, f2p, f2b, ret, F, nullptr, nullptr, Pp, Cc, DIN, 0, stats);

        bn_stats<<<Pp / 64, 256>>>(F, stats, Pp);

        if (ly == 0) {
            // fused BN(leaky)+LN into next layer's normalized input (no X round-trip)
            bnln_kernel<<<Pp / 8, 256>>>(F, stats, fbg, fbb,
                                         ln_g + Cc, ln_b + Cc, xn, xnh, xnl);
        } else {
            // fused BN(leaky)+transpose to output
            bnfinal_kernel<<<(TOTAL + 255) / 256, 256>>>(F, stats, fbg, fbb,
                                                         (float*)d_out);
        }
    }
}